// round 10
// baseline (speedup 1.0000x reference)
#include <cuda_runtime.h>
#include <cuda_bf16.h>
#include <cstdint>

#define EMBED 1024
#define NHEAD 16
#define HDIM  64
#define BATCH 2
#define SEQ   2048
#define MTOT  (BATCH*SEQ)   /* 4096 */

// Scratch (device globals: allocation-free per harness rules)
__device__ float g_q[MTOT*EMBED];            // fp32, [B,H,S,Dh]
__device__ float g_attn[MTOT*EMBED];         // fp32, [B,S,E]
__device__ __nv_bfloat16 g_k_hi[MTOT*EMBED]; // bf16 split, [B,H,S,Dh]
__device__ __nv_bfloat16 g_k_lo[MTOT*EMBED];
__device__ __nv_bfloat16 g_v_hi[MTOT*EMBED];
__device__ __nv_bfloat16 g_v_lo[MTOT*EMBED];
// pre-split GEMM operands
__device__ __nv_bfloat16 g_xh[MTOT*EMBED], g_xl[MTOT*EMBED];
__device__ __nv_bfloat16 g_ah[MTOT*EMBED], g_al[MTOT*EMBED];
__device__ __nv_bfloat16 g_wqh[EMBED*EMBED], g_wql[EMBED*EMBED];
__device__ __nv_bfloat16 g_wkh[EMBED*EMBED], g_wkl[EMBED*EMBED];
__device__ __nv_bfloat16 g_wvh[EMBED*EMBED], g_wvl[EMBED*EMBED];
__device__ __nv_bfloat16 g_woh[EMBED*EMBED], g_wol[EMBED*EMBED];

// ---------------------------------------------------------------------------
// helpers
// ---------------------------------------------------------------------------
__device__ __forceinline__ uint32_t s2u(const void* p) {
    return (uint32_t)__cvta_generic_to_shared(p);
}
__device__ __forceinline__ void ldm_x4(uint32_t& r0, uint32_t& r1, uint32_t& r2,
                                       uint32_t& r3, uint32_t addr) {
    asm volatile("ldmatrix.sync.aligned.m8n8.x4.shared.b16 {%0,%1,%2,%3}, [%4];"
                 : "=r"(r0), "=r"(r1), "=r"(r2), "=r"(r3) : "r"(addr));
}
__device__ __forceinline__ void ldm_x2(uint32_t& r0, uint32_t& r1, uint32_t addr) {
    asm volatile("ldmatrix.sync.aligned.m8n8.x2.shared.b16 {%0,%1}, [%2];"
                 : "=r"(r0), "=r"(r1) : "r"(addr));
}
__device__ __forceinline__ void ldmT_x2(uint32_t& r0, uint32_t& r1, uint32_t addr) {
    asm volatile("ldmatrix.sync.aligned.m8n8.x2.trans.shared.b16 {%0,%1}, [%2];"
                 : "=r"(r0), "=r"(r1) : "r"(addr));
}
__device__ __forceinline__ void mma16(float* c, uint32_t a0, uint32_t a1,
                                      uint32_t a2, uint32_t a3,
                                      uint32_t b0, uint32_t b1) {
    asm volatile(
        "mma.sync.aligned.m16n8k16.row.col.f32.bf16.bf16.f32 "
        "{%0,%1,%2,%3}, {%4,%5,%6,%7}, {%8,%9}, {%0,%1,%2,%3};"
        : "+f"(c[0]), "+f"(c[1]), "+f"(c[2]), "+f"(c[3])
        : "r"(a0), "r"(a1), "r"(a2), "r"(a3), "r"(b0), "r"(b1));
}
__device__ __forceinline__ void cp16(uint32_t dst, const void* src) {
    asm volatile("cp.async.cg.shared.global [%0], [%1], 16;" :: "r"(dst), "l"(src));
}
#define CP_COMMIT() asm volatile("cp.async.commit_group;")
#define CP_WAIT0()  asm volatile("cp.async.wait_group 0;")
#define CP_WAIT1()  asm volatile("cp.async.wait_group 1;")

// split fp32x4 -> (hi bf16x2 pair, lo bf16x2 pair)
__device__ __forceinline__ void split4(float4 v,
        __nv_bfloat162& h01, __nv_bfloat162& h23,
        __nv_bfloat162& l01, __nv_bfloat162& l23) {
    h01 = __floats2bfloat162_rn(v.x, v.y);
    h23 = __floats2bfloat162_rn(v.z, v.w);
    float2 f01 = __bfloat1622float2(h01);
    float2 f23 = __bfloat1622float2(h23);
    l01 = __floats2bfloat162_rn(v.x - f01.x, v.y - f01.y);
    l23 = __floats2bfloat162_rn(v.z - f23.x, v.w - f23.y);
}
__device__ __forceinline__ void store_split2(__nv_bfloat16* ph, __nv_bfloat16* pl,
                                             size_t off, float x, float y) {
    __nv_bfloat162 h = __floats2bfloat162_rn(x, y);
    float2 hf = __bfloat1622float2(h);
    __nv_bfloat162 l = __floats2bfloat162_rn(x - hf.x, y - hf.y);
    *(__nv_bfloat162*)&ph[off] = h;
    *(__nv_bfloat162*)&pl[off] = l;
}
// pack two fp32 to bf16x2 (hi) + residual bf16x2 (lo), as uint32
__device__ __forceinline__ void pack_hl(float x, float y, uint32_t& hi, uint32_t& lo) {
    __nv_bfloat162 h = __floats2bfloat162_rn(x, y);
    float2 hf = __bfloat1622float2(h);
    __nv_bfloat162 l = __floats2bfloat162_rn(x - hf.x, y - hf.y);
    hi = *(uint32_t*)&h;
    lo = *(uint32_t*)&l;
}

// ---------------------------------------------------------------------------
// split kernel: fp32 tensor -> bf16 hi/lo pair.
// sel: 0=x, 1=Wq, 2=Wk, 3=Wv, 4=Wo, 5=g_attn(src internal)
// ---------------------------------------------------------------------------
__global__ void split_f32(const float4* __restrict__ src, int sel, int n4)
{
    __nv_bfloat16 *dh, *dl;
    if      (sel == 0) { dh = g_xh;  dl = g_xl;  }
    else if (sel == 1) { dh = g_wqh; dl = g_wql; }
    else if (sel == 2) { dh = g_wkh; dl = g_wkl; }
    else if (sel == 3) { dh = g_wvh; dl = g_wvl; }
    else if (sel == 4) { dh = g_woh; dl = g_wol; }
    else               { dh = g_ah;  dl = g_al;  src = (const float4*)g_attn; }

    int i = blockIdx.x * blockDim.x + threadIdx.x;
    if (i < n4) {
        float4 v = src[i];
        __nv_bfloat162 h01, h23, l01, l23;
        split4(v, h01, h23, l01, l23);
        *(__nv_bfloat162*)&dh[4 * i]     = h01;
        *(__nv_bfloat162*)&dh[4 * i + 2] = h23;
        *(__nv_bfloat162*)&dl[4 * i]     = l01;
        *(__nv_bfloat162*)&dl[4 * i + 2] = l23;
    }
}

// ---------------------------------------------------------------------------
// GEMM (bf16x3, mma.sync, pre-split inputs): C[4096,1024] = A @ W^T + bias
// 128x128 tile, kc=16, 3-stage cp.async, 256 threads (8 warps, 64x32 warp tile)
// mode 0: -> g_q fp32 [B,H,S,Dh]; 1: -> g_k hi/lo; 2: -> g_v hi/lo;
// mode 3: A=g_ah/g_al -> outp fp32 [M,N]
// ---------------------------------------------------------------------------
#define GST 24                 /* smem k-stride in bf16 elems (16 + 8 pad) */
#define TSZ (128 * GST * 2)    /* 6144 B per tensor */
#define STG (4 * TSZ)          /* 24576 B per stage */
#define GEMM_SMEM (3 * STG)    /* 73728 B */
#define NCHUNK 64

__global__ __launch_bounds__(256, 2) void gemm_ms(
    const float* __restrict__ bias, float* __restrict__ outp, int mode)
{
    extern __shared__ char gsm[];
    const uint32_t smu = s2u(gsm);

    const __nv_bfloat16 *Agh, *Agl, *Wgh, *Wgl;
    if (mode == 3) { Agh = g_ah; Agl = g_al; }
    else           { Agh = g_xh; Agl = g_xl; }
    if      (mode == 0) { Wgh = g_wqh; Wgl = g_wql; }
    else if (mode == 1) { Wgh = g_wkh; Wgl = g_wkl; }
    else if (mode == 2) { Wgh = g_wvh; Wgl = g_wvl; }
    else                { Wgh = g_woh; Wgl = g_wol; }

    const int t    = threadIdx.x;
    const int lane = t & 31;
    const int w    = t >> 5;
    const int wm   = w >> 2;        // 0..1  (64 rows each)
    const int wn   = w & 3;         // 0..3  (32 cols each)
    const int m0   = blockIdx.y * 128;
    const int n0   = blockIdx.x * 128;

    const int t4    = lane & 3;
    const int g     = lane >> 2;
    const int l15   = lane & 15;
    const int row_l = (lane & 7) + ((lane >> 3) & 1) * 8;
    const int khalf = lane >> 4;

    const uint32_t a_off = (uint32_t)(((wm * 64 + row_l) * GST + khalf * 8) * 2);
    const uint32_t b_off = (uint32_t)(((wn * 32 + (l15 & 7)) * GST + (l15 >> 3) * 8) * 2);

    // per-thread load slot: row = t>>1 (0..127), ch = t&1 (16B halves of 32B row)
    const int lrow = t >> 1, lch = t & 1;
    const uint32_t lso = (uint32_t)(lrow * (GST * 2) + lch * 16);
    const size_t agbase = (size_t)(m0 + lrow) * EMBED + lch * 8;
    const size_t bgbase = (size_t)(n0 + lrow) * EMBED + lch * 8;

    float c[4][4][4];
#pragma unroll
    for (int mi = 0; mi < 4; mi++)
#pragma unroll
        for (int nj = 0; nj < 4; nj++)
#pragma unroll
            for (int i = 0; i < 4; i++) c[mi][nj][i] = 0.f;

    auto load_chunk = [&](int kb, uint32_t sb) {
        const int kofs = kb * 16;
        cp16(sb + lso,            Agh + agbase + kofs);
        cp16(sb + TSZ + lso,      Agl + agbase + kofs);
        cp16(sb + 2 * TSZ + lso,  Wgh + bgbase + kofs);
        cp16(sb + 3 * TSZ + lso,  Wgl + bgbase + kofs);
    };

    load_chunk(0, smu);           CP_COMMIT();
    load_chunk(1, smu + STG);     CP_COMMIT();

    for (int kb = 0; kb < NCHUNK; kb++) {
        if (kb + 1 < NCHUNK) { CP_WAIT1(); } else { CP_WAIT0(); }
        __syncthreads();
        if (kb + 2 < NCHUNK) {
            load_chunk(kb + 2, smu + (uint32_t)(((kb + 2) % 3) * STG));
            CP_COMMIT();
        }

        const uint32_t sb = smu + (uint32_t)((kb % 3) * STG);
        uint32_t Bh[4][2], Bl[4][2];
#pragma unroll
        for (int nj = 0; nj < 4; nj++) {
            ldm_x2(Bh[nj][0], Bh[nj][1], sb + 2 * TSZ + b_off + (uint32_t)(nj * 8 * GST * 2));
            ldm_x2(Bl[nj][0], Bl[nj][1], sb + 3 * TSZ + b_off + (uint32_t)(nj * 8 * GST * 2));
        }
#pragma unroll
        for (int mi = 0; mi < 4; mi++) {
            uint32_t ah0, ah1, ah2, ah3, al0, al1, al2, al3;
            uint32_t ao = a_off + (uint32_t)(mi * 16 * GST * 2);
            ldm_x4(ah0, ah1, ah2, ah3, sb + ao);
            ldm_x4(al0, al1, al2, al3, sb + TSZ + ao);
#pragma unroll
            for (int nj = 0; nj < 4; nj++) {
                mma16(c[mi][nj], al0, al1, al2, al3, Bh[nj][0], Bh[nj][1]);
                mma16(c[mi][nj], ah0, ah1, ah2, ah3, Bl[nj][0], Bl[nj][1]);
                mma16(c[mi][nj], ah0, ah1, ah2, ah3, Bh[nj][0], Bh[nj][1]);
            }
        }
    }

    // epilogue
#pragma unroll
    for (int mi = 0; mi < 4; mi++) {
        int r0 = m0 + wm * 64 + mi * 16 + g;
        int r1 = r0 + 8;
#pragma unroll
        for (int nj = 0; nj < 4; nj++) {
            int col = n0 + wn * 32 + nj * 8 + 2 * t4;
            float bb0 = bias[col], bb1 = bias[col + 1];
            float v00 = c[mi][nj][0] + bb0, v01 = c[mi][nj][1] + bb1;
            float v10 = c[mi][nj][2] + bb0, v11 = c[mi][nj][3] + bb1;
            if (mode == 3) {
                *(float2*)&outp[(size_t)r0 * EMBED + col] = make_float2(v00, v01);
                *(float2*)&outp[(size_t)r1 * EMBED + col] = make_float2(v10, v11);
            } else {
                int h  = col >> 6, dh = col & 63;
                int b0i = r0 >> 11, s0i = r0 & 2047;
                int b1i = r1 >> 11, s1i = r1 & 2047;
                size_t o0 = (((size_t)(b0i * NHEAD + h)) * SEQ + s0i) * HDIM + dh;
                size_t o1 = (((size_t)(b1i * NHEAD + h)) * SEQ + s1i) * HDIM + dh;
                if (mode == 0) {
                    *(float2*)&g_q[o0] = make_float2(v00, v01);
                    *(float2*)&g_q[o1] = make_float2(v10, v11);
                } else if (mode == 1) {
                    store_split2(g_k_hi, g_k_lo, o0, v00, v01);
                    store_split2(g_k_hi, g_k_lo, o1, v10, v11);
                } else {
                    store_split2(g_v_hi, g_v_lo, o0, v00, v01);
                    store_split2(g_v_hi, g_v_lo, o1, v10, v11);
                }
            }
        }
    }
}

// ---------------------------------------------------------------------------
// Flash attention (bf16x3): AQ=128 (8 warps x 16 rows), BK=64,
// cp.async double-buffered pre-split K/V, in-register online softmax,
// register-resident P (C-fragment of S reused as A-fragment for PV).
// ---------------------------------------------------------------------------
#define AQ  128
#define AK  64
#define NIT (SEQ / AK)   /* 32 */
#define QST 72
#define KST 72
#define VST 72

/* byte offsets inside dynamic smem */
#define OQH 0
#define OQL 18432
#define OKH 36864     /* 2 bufs x 9216 */
#define OKL 55296
#define OVH 73728
#define OVL 92160
#define OMK 110592    /* 2 bufs x 256B */
#define ATTN_SMEM_B 111104
#define KBUF 9216     /* bytes per K/V tensor buffer (64*72*2) */

__global__ __launch_bounds__(256, 2) void attn_bf16(const int* __restrict__ mask)
{
    extern __shared__ char smraw[];
    const uint32_t sm_u = s2u(smraw);

    __nv_bfloat16* Qh = (__nv_bfloat16*)(smraw + OQH);
    __nv_bfloat16* Ql = (__nv_bfloat16*)(smraw + OQL);
    int* mks = (int*)(smraw + OMK);

    const int t    = threadIdx.x;
    const int lane = t & 31;
    const int w    = t >> 5;            // 0..7, warp owns rows w*16..+15
    const int bh   = blockIdx.y;
    const int b    = bh >> 4;
    const int h    = bh & 15;
    const int q0   = blockIdx.x * AQ;

    const int t4    = lane & 3;
    const int g     = lane >> 2;
    const int l15   = lane & 15;
    const int row_l = (lane & 7) + ((lane >> 3) & 1) * 8;
    const int khalf = lane >> 4;

    const float* Qg = g_q + (size_t)bh * SEQ * HDIM;
    const __nv_bfloat16* Kgh = g_k_hi + (size_t)bh * SEQ * HDIM;
    const __nv_bfloat16* Kgl = g_k_lo + (size_t)bh * SEQ * HDIM;
    const __nv_bfloat16* Vgh = g_v_hi + (size_t)bh * SEQ * HDIM;
    const __nv_bfloat16* Vgl = g_v_lo + (size_t)bh * SEQ * HDIM;

    const uint32_t qah = sm_u + OQH + (uint32_t)(((w * 16 + row_l) * QST + khalf * 8) * 2);
    const uint32_t qal = sm_u + OQL + (uint32_t)(((w * 16 + row_l) * QST + khalf * 8) * 2);
    const uint32_t kboff = (uint32_t)(((l15 & 7) * KST + (l15 >> 3) * 8) * 2);
    const uint32_t vboff = (uint32_t)((((l15 & 7) + 8 * (l15 >> 3)) * VST) * 2);

    // K/V loader: 2 slots/thread/tensor: row = idx>>3 (0..63), ch = idx&7
    auto load_kv = [&](int it, int bufi) {
        const uint32_t bo = (uint32_t)(bufi * KBUF);
        const size_t kofs = (size_t)it * AK * HDIM;
#pragma unroll
        for (int l = 0; l < 2; l++) {
            int i = l * 256 + t;
            int row = i >> 3, ch = i & 7;
            uint32_t so = (uint32_t)((row * KST + ch * 8) * 2);
            size_t go = kofs + (size_t)row * HDIM + ch * 8;
            cp16(sm_u + OKH + bo + so, Kgh + go);
            cp16(sm_u + OKL + bo + so, Kgl + go);
            cp16(sm_u + OVH + bo + so, Vgh + go);
            cp16(sm_u + OVL + bo + so, Vgl + go);
        }
        if (t < 16) cp16(sm_u + OMK + (uint32_t)(bufi * 256 + t * 16),
                         mask + b * SEQ + it * AK + t * 4);
    };

    load_kv(0, 0);
    CP_COMMIT();

    // ---- load Q (x0.125), split to bf16 hi/lo in smem ----
#pragma unroll
    for (int l = 0; l < 8; l++) {
        int e = l * 256 + t, row = e >> 4, seg = e & 15;
        float4 v = *(const float4*)&Qg[(size_t)(q0 + row) * HDIM + seg * 4];
        v.x *= 0.125f; v.y *= 0.125f; v.z *= 0.125f; v.w *= 0.125f;
        __nv_bfloat162 h01, h23, l01, l23;
        split4(v, h01, h23, l01, l23);
        int off = row * QST + seg * 4;
        *(__nv_bfloat162*)&Qh[off]     = h01;
        *(__nv_bfloat162*)&Qh[off + 2] = h23;
        *(__nv_bfloat162*)&Ql[off]     = l01;
        *(__nv_bfloat162*)&Ql[off + 2] = l23;
    }

    float o[8][4];
#pragma unroll
    for (int j = 0; j < 8; j++)
#pragma unroll
        for (int i = 0; i < 4; i++) o[j][i] = 0.f;
    float m0 = -1e30f, m1 = -1e30f, l0 = 0.f, l1 = 0.f;

    __syncthreads();   // Q visible; tile0 still in flight

    for (int it = 0; it < NIT; it++) {
        const int buf = it & 1;
        if (it + 1 < NIT) {
            load_kv(it + 1, buf ^ 1);
            CP_COMMIT();
            CP_WAIT1();
        } else {
            CP_WAIT0();
        }
        __syncthreads();

        const uint32_t khb = sm_u + OKH + (uint32_t)(buf * KBUF) + kboff;
        const uint32_t klb = sm_u + OKL + (uint32_t)(buf * KBUF) + kboff;
        const uint32_t vhb = sm_u + OVH + (uint32_t)(buf * KBUF) + vboff;
        const uint32_t vlb = sm_u + OVL + (uint32_t)(buf * KBUF) + vboff;
        const int* mk = mks + buf * 64;

        // ---- S = Q K^T  (16 x 64 per warp) ----
        float s[8][4];
#pragma unroll
        for (int j = 0; j < 8; j++)
#pragma unroll
            for (int i = 0; i < 4; i++) s[j][i] = 0.f;

#pragma unroll
        for (int ks = 0; ks < 4; ks++) {
            uint32_t ah0, ah1, ah2, ah3, al0, al1, al2, al3;
            ldm_x4(ah0, ah1, ah2, ah3, qah + (uint32_t)(ks * 32));
            ldm_x4(al0, al1, al2, al3, qal + (uint32_t)(ks * 32));
#pragma unroll
            for (int j = 0; j < 8; j++) {
                uint32_t bh0, bh1, bl0, bl1;
                uint32_t off = (uint32_t)(j * 8 * KST * 2 + ks * 32);
                ldm_x2(bh0, bh1, khb + off);
                ldm_x2(bl0, bl1, klb + off);
                mma16(s[j], al0, al1, al2, al3, bh0, bh1);
                mma16(s[j], ah0, ah1, ah2, ah3, bl0, bl1);
                mma16(s[j], ah0, ah1, ah2, ah3, bh0, bh1);
            }
        }

        // ---- mask + online softmax (rows r0 = w*16+g, r1 = +8) ----
        float mx0 = -1e30f, mx1 = -1e30f;
#pragma unroll
        for (int j = 0; j < 8; j++) {
            int cb = j * 8 + 2 * t4;
            if (mk[cb] == 0)     { s[j][0] = -1e9f; s[j][2] = -1e9f; }
            if (mk[cb + 1] == 0) { s[j][1] = -1e9f; s[j][3] = -1e9f; }
            mx0 = fmaxf(mx0, fmaxf(s[j][0], s[j][1]));
            mx1 = fmaxf(mx1, fmaxf(s[j][2], s[j][3]));
        }
        mx0 = fmaxf(mx0, __shfl_xor_sync(0xffffffffu, mx0, 1));
        mx0 = fmaxf(mx0, __shfl_xor_sync(0xffffffffu, mx0, 2));
        mx1 = fmaxf(mx1, __shfl_xor_sync(0xffffffffu, mx1, 1));
        mx1 = fmaxf(mx1, __shfl_xor_sync(0xffffffffu, mx1, 2));

        float mn0 = fmaxf(m0, mx0), mn1 = fmaxf(m1, mx1);
        float f0 = __expf(m0 - mn0), f1 = __expf(m1 - mn1);
        m0 = mn0; m1 = mn1;

        float sum0 = 0.f, sum1 = 0.f;
#pragma unroll
        for (int j = 0; j < 8; j++) {
            s[j][0] = __expf(s[j][0] - m0);
            s[j][1] = __expf(s[j][1] - m0);
            s[j][2] = __expf(s[j][2] - m1);
            s[j][3] = __expf(s[j][3] - m1);
            sum0 += s[j][0] + s[j][1];
            sum1 += s[j][2] + s[j][3];
        }
        sum0 += __shfl_xor_sync(0xffffffffu, sum0, 1);
        sum0 += __shfl_xor_sync(0xffffffffu, sum0, 2);
        sum1 += __shfl_xor_sync(0xffffffffu, sum1, 1);
        sum1 += __shfl_xor_sync(0xffffffffu, sum1, 2);
        l0 = l0 * f0 + sum0;
        l1 = l1 * f1 + sum1;

#pragma unroll
        for (int j = 0; j < 8; j++) {
            o[j][0] *= f0; o[j][1] *= f0; o[j][2] *= f1; o[j][3] *= f1;
        }

        // ---- O += P V : P packed in registers from S fragments ----
#pragma unroll
        for (int ks = 0; ks < 4; ks++) {
            // A-fragment for keys [16ks, 16ks+16): tiles j0=2ks (k 0-7), j1=2ks+1 (k 8-15)
            uint32_t ph0, ph1, ph2, ph3, pl0, pl1, pl2, pl3;
            pack_hl(s[2 * ks][0],     s[2 * ks][1],     ph0, pl0);
            pack_hl(s[2 * ks][2],     s[2 * ks][3],     ph1, pl1);
            pack_hl(s[2 * ks + 1][0], s[2 * ks + 1][1], ph2, pl2);
            pack_hl(s[2 * ks + 1][2], s[2 * ks + 1][3], ph3, pl3);
#pragma unroll
            for (int j = 0; j < 8; j++) {
                uint32_t vh0, vh1, vl0, vl1;
                uint32_t off = (uint32_t)(ks * 16 * VST * 2 + j * 16);
                ldmT_x2(vh0, vh1, vhb + off);
                ldmT_x2(vl0, vl1, vlb + off);
                mma16(o[j], pl0, pl1, pl2, pl3, vh0, vh1);
                mma16(o[j], ph0, ph1, ph2, ph3, vl0, vl1);
                mma16(o[j], ph0, ph1, ph2, ph3, vh0, vh1);
            }
        }
        __syncthreads();
    }

    // ---- epilogue: normalize + write g_attn [b, s, h*64+d] fp32 ----
    float il0 = 1.f / l0, il1 = 1.f / l1;
    size_t base0 = ((size_t)b * SEQ + q0 + w * 16 + g) * EMBED + h * HDIM;
    size_t base1 = base0 + (size_t)8 * EMBED;
#pragma unroll
    for (int j = 0; j < 8; j++) {
        int col = j * 8 + 2 * t4;
        *(float2*)&g_attn[base0 + col] = make_float2(o[j][0] * il0, o[j][1] * il0);
        *(float2*)&g_attn[base1 + col] = make_float2(o[j][2] * il1, o[j][3] * il1);
    }
}

// ---------------------------------------------------------------------------
extern "C" void kernel_launch(void* const* d_in, const int* in_sizes, int n_in,
                              void* d_out, int out_size)
{
    const float* x    = (const float*)d_in[0];
    const int*   mask = (const int*)  d_in[1];
    const float* Wq   = (const float*)d_in[2];
    const float* bq   = (const float*)d_in[3];
    const float* Wk   = (const float*)d_in[4];
    const float* bk   = (const float*)d_in[5];
    const float* Wv   = (const float*)d_in[6];
    const float* bv   = (const float*)d_in[7];
    const float* Wo   = (const float*)d_in[8];
    const float* bo   = (const float*)d_in[9];
    float* out = (float*)d_out;

    cudaFuncSetAttribute(attn_bf16,
                         cudaFuncAttributeMaxDynamicSharedMemorySize, ATTN_SMEM_B);
    cudaFuncSetAttribute(gemm_ms,
                         cudaFuncAttributeMaxDynamicSharedMemorySize, GEMM_SMEM);

    const int NX4 = MTOT * EMBED / 4;    // 1,048,576
    const int NW4 = EMBED * EMBED / 4;   //   262,144

    split_f32<<<(NX4 + 255) / 256, 256>>>((const float4*)x,  0, NX4);
    split_f32<<<(NW4 + 255) / 256, 256>>>((const float4*)Wq, 1, NW4);
    split_f32<<<(NW4 + 255) / 256, 256>>>((const float4*)Wk, 2, NW4);
    split_f32<<<(NW4 + 255) / 256, 256>>>((const float4*)Wv, 3, NW4);
    split_f32<<<(NW4 + 255) / 256, 256>>>((const float4*)Wo, 4, NW4);

    dim3 gg(EMBED / 128, MTOT / 128);    // (8, 32) = 256 CTAs
    gemm_ms<<<gg, 256, GEMM_SMEM>>>(bq, nullptr, 0);
    gemm_ms<<<gg, 256, GEMM_SMEM>>>(bk, nullptr, 1);
    gemm_ms<<<gg, 256, GEMM_SMEM>>>(bv, nullptr, 2);

    attn_bf16<<<dim3(SEQ / AQ, BATCH * NHEAD), 256, ATTN_SMEM_B>>>(mask);

    split_f32<<<(NX4 + 255) / 256, 256>>>(nullptr, 5, NX4);
    gemm_ms<<<gg, 256, GEMM_SMEM>>>(bo, out, 3);
}

// round 11
// speedup vs baseline: 1.4854x; 1.4854x over previous
#include <cuda_runtime.h>
#include <cuda_bf16.h>
#include <cstdint>

#define EMBED 1024
#define NHEAD 16
#define HDIM  64
#define BATCH 2
#define SEQ   2048
#define MTOT  (BATCH*SEQ)   /* 4096 */

// Scratch (device globals: allocation-free per harness rules)
__device__ float g_q[MTOT*EMBED];            // fp32, [B,H,S,Dh]
__device__ float g_attn[MTOT*EMBED];         // fp32, [B,S,E]
__device__ __nv_bfloat16 g_k_hi[MTOT*EMBED]; // bf16 split, [B,H,S,Dh]
__device__ __nv_bfloat16 g_k_lo[MTOT*EMBED];
__device__ __nv_bfloat16 g_v_hi[MTOT*EMBED];
__device__ __nv_bfloat16 g_v_lo[MTOT*EMBED];
// pre-split GEMM operands
__device__ __nv_bfloat16 g_xh[MTOT*EMBED], g_xl[MTOT*EMBED];
__device__ __nv_bfloat16 g_ah[MTOT*EMBED], g_al[MTOT*EMBED];
__device__ __nv_bfloat16 g_wqh[EMBED*EMBED], g_wql[EMBED*EMBED];
__device__ __nv_bfloat16 g_wkh[EMBED*EMBED], g_wkl[EMBED*EMBED];
__device__ __nv_bfloat16 g_wvh[EMBED*EMBED], g_wvl[EMBED*EMBED];
__device__ __nv_bfloat16 g_woh[EMBED*EMBED], g_wol[EMBED*EMBED];

// ---------------------------------------------------------------------------
// helpers
// ---------------------------------------------------------------------------
__device__ __forceinline__ uint32_t s2u(const void* p) {
    return (uint32_t)__cvta_generic_to_shared(p);
}
__device__ __forceinline__ void ldm_x4(uint32_t& r0, uint32_t& r1, uint32_t& r2,
                                       uint32_t& r3, uint32_t addr) {
    asm volatile("ldmatrix.sync.aligned.m8n8.x4.shared.b16 {%0,%1,%2,%3}, [%4];"
                 : "=r"(r0), "=r"(r1), "=r"(r2), "=r"(r3) : "r"(addr));
}
__device__ __forceinline__ void ldm_x2(uint32_t& r0, uint32_t& r1, uint32_t addr) {
    asm volatile("ldmatrix.sync.aligned.m8n8.x2.shared.b16 {%0,%1}, [%2];"
                 : "=r"(r0), "=r"(r1) : "r"(addr));
}
__device__ __forceinline__ void ldmT_x2(uint32_t& r0, uint32_t& r1, uint32_t addr) {
    asm volatile("ldmatrix.sync.aligned.m8n8.x2.trans.shared.b16 {%0,%1}, [%2];"
                 : "=r"(r0), "=r"(r1) : "r"(addr));
}
__device__ __forceinline__ void mma16(float* c, uint32_t a0, uint32_t a1,
                                      uint32_t a2, uint32_t a3,
                                      uint32_t b0, uint32_t b1) {
    asm volatile(
        "mma.sync.aligned.m16n8k16.row.col.f32.bf16.bf16.f32 "
        "{%0,%1,%2,%3}, {%4,%5,%6,%7}, {%8,%9}, {%0,%1,%2,%3};"
        : "+f"(c[0]), "+f"(c[1]), "+f"(c[2]), "+f"(c[3])
        : "r"(a0), "r"(a1), "r"(a2), "r"(a3), "r"(b0), "r"(b1));
}
__device__ __forceinline__ void cp16(uint32_t dst, const void* src) {
    asm volatile("cp.async.cg.shared.global [%0], [%1], 16;" :: "r"(dst), "l"(src));
}
#define CP_COMMIT() asm volatile("cp.async.commit_group;")
#define CP_WAIT0()  asm volatile("cp.async.wait_group 0;")
#define CP_WAIT1()  asm volatile("cp.async.wait_group 1;")

// split fp32x4 -> (hi bf16x2 pair, lo bf16x2 pair)
__device__ __forceinline__ void split4(float4 v,
        __nv_bfloat162& h01, __nv_bfloat162& h23,
        __nv_bfloat162& l01, __nv_bfloat162& l23) {
    h01 = __floats2bfloat162_rn(v.x, v.y);
    h23 = __floats2bfloat162_rn(v.z, v.w);
    float2 f01 = __bfloat1622float2(h01);
    float2 f23 = __bfloat1622float2(h23);
    l01 = __floats2bfloat162_rn(v.x - f01.x, v.y - f01.y);
    l23 = __floats2bfloat162_rn(v.z - f23.x, v.w - f23.y);
}
__device__ __forceinline__ void store_split2(__nv_bfloat16* ph, __nv_bfloat16* pl,
                                             size_t off, float x, float y) {
    __nv_bfloat162 h = __floats2bfloat162_rn(x, y);
    float2 hf = __bfloat1622float2(h);
    __nv_bfloat162 l = __floats2bfloat162_rn(x - hf.x, y - hf.y);
    *(__nv_bfloat162*)&ph[off] = h;
    *(__nv_bfloat162*)&pl[off] = l;
}

// ---------------------------------------------------------------------------
// split kernel: fp32 tensor -> bf16 hi/lo pair.
// sel: 0=x, 1=Wq, 2=Wk, 3=Wv, 4=Wo, 5=g_attn(src internal)
// ---------------------------------------------------------------------------
__global__ void split_f32(const float4* __restrict__ src, int sel, int n4)
{
    __nv_bfloat16 *dh, *dl;
    if      (sel == 0) { dh = g_xh;  dl = g_xl;  }
    else if (sel == 1) { dh = g_wqh; dl = g_wql; }
    else if (sel == 2) { dh = g_wkh; dl = g_wkl; }
    else if (sel == 3) { dh = g_wvh; dl = g_wvl; }
    else if (sel == 4) { dh = g_woh; dl = g_wol; }
    else               { dh = g_ah;  dl = g_al;  src = (const float4*)g_attn; }

    int i = blockIdx.x * blockDim.x + threadIdx.x;
    if (i < n4) {
        float4 v = src[i];
        __nv_bfloat162 h01, h23, l01, l23;
        split4(v, h01, h23, l01, l23);
        *(__nv_bfloat162*)&dh[4 * i]     = h01;
        *(__nv_bfloat162*)&dh[4 * i + 2] = h23;
        *(__nv_bfloat162*)&dl[4 * i]     = l01;
        *(__nv_bfloat162*)&dl[4 * i + 2] = l23;
    }
}

// ---------------------------------------------------------------------------
// GEMM (bf16x3, mma.sync, pre-split inputs): C[4096,1024] = A @ W^T + bias
// 128x128 tile, kc=16, 3-stage cp.async, 256 threads (8 warps, 64x32 warp tile)
// ---------------------------------------------------------------------------
#define GST 24                 /* smem k-stride in bf16 elems (16 + 8 pad) */
#define TSZ (128 * GST * 2)    /* 6144 B per tensor */
#define STG (4 * TSZ)          /* 24576 B per stage */
#define GEMM_SMEM (3 * STG)    /* 73728 B */
#define NCHUNK 64

__global__ __launch_bounds__(256, 2) void gemm_ms(
    const float* __restrict__ bias, float* __restrict__ outp, int mode)
{
    extern __shared__ char gsm[];
    const uint32_t smu = s2u(gsm);

    const __nv_bfloat16 *Agh, *Agl, *Wgh, *Wgl;
    if (mode == 3) { Agh = g_ah; Agl = g_al; }
    else           { Agh = g_xh; Agl = g_xl; }
    if      (mode == 0) { Wgh = g_wqh; Wgl = g_wql; }
    else if (mode == 1) { Wgh = g_wkh; Wgl = g_wkl; }
    else if (mode == 2) { Wgh = g_wvh; Wgl = g_wvl; }
    else                { Wgh = g_woh; Wgl = g_wol; }

    const int t    = threadIdx.x;
    const int lane = t & 31;
    const int w    = t >> 5;
    const int wm   = w >> 2;
    const int wn   = w & 3;
    const int m0   = blockIdx.y * 128;
    const int n0   = blockIdx.x * 128;

    const int t4    = lane & 3;
    const int g     = lane >> 2;
    const int l15   = lane & 15;
    const int row_l = (lane & 7) + ((lane >> 3) & 1) * 8;
    const int khalf = lane >> 4;

    const uint32_t a_off = (uint32_t)(((wm * 64 + row_l) * GST + khalf * 8) * 2);
    const uint32_t b_off = (uint32_t)(((wn * 32 + (l15 & 7)) * GST + (l15 >> 3) * 8) * 2);

    const int lrow = t >> 1, lch = t & 1;
    const uint32_t lso = (uint32_t)(lrow * (GST * 2) + lch * 16);
    const size_t agbase = (size_t)(m0 + lrow) * EMBED + lch * 8;
    const size_t bgbase = (size_t)(n0 + lrow) * EMBED + lch * 8;

    float c[4][4][4];
#pragma unroll
    for (int mi = 0; mi < 4; mi++)
#pragma unroll
        for (int nj = 0; nj < 4; nj++)
#pragma unroll
            for (int i = 0; i < 4; i++) c[mi][nj][i] = 0.f;

    auto load_chunk = [&](int kb, uint32_t sb) {
        const int kofs = kb * 16;
        cp16(sb + lso,            Agh + agbase + kofs);
        cp16(sb + TSZ + lso,      Agl + agbase + kofs);
        cp16(sb + 2 * TSZ + lso,  Wgh + bgbase + kofs);
        cp16(sb + 3 * TSZ + lso,  Wgl + bgbase + kofs);
    };

    load_chunk(0, smu);           CP_COMMIT();
    load_chunk(1, smu + STG);     CP_COMMIT();

    for (int kb = 0; kb < NCHUNK; kb++) {
        if (kb + 1 < NCHUNK) { CP_WAIT1(); } else { CP_WAIT0(); }
        __syncthreads();
        if (kb + 2 < NCHUNK) {
            load_chunk(kb + 2, smu + (uint32_t)(((kb + 2) % 3) * STG));
            CP_COMMIT();
        }

        const uint32_t sb = smu + (uint32_t)((kb % 3) * STG);
        uint32_t Bh[4][2], Bl[4][2];
#pragma unroll
        for (int nj = 0; nj < 4; nj++) {
            ldm_x2(Bh[nj][0], Bh[nj][1], sb + 2 * TSZ + b_off + (uint32_t)(nj * 8 * GST * 2));
            ldm_x2(Bl[nj][0], Bl[nj][1], sb + 3 * TSZ + b_off + (uint32_t)(nj * 8 * GST * 2));
        }
#pragma unroll
        for (int mi = 0; mi < 4; mi++) {
            uint32_t ah0, ah1, ah2, ah3, al0, al1, al2, al3;
            uint32_t ao = a_off + (uint32_t)(mi * 16 * GST * 2);
            ldm_x4(ah0, ah1, ah2, ah3, sb + ao);
            ldm_x4(al0, al1, al2, al3, sb + TSZ + ao);
#pragma unroll
            for (int nj = 0; nj < 4; nj++) {
                mma16(c[mi][nj], al0, al1, al2, al3, Bh[nj][0], Bh[nj][1]);
                mma16(c[mi][nj], ah0, ah1, ah2, ah3, Bl[nj][0], Bl[nj][1]);
                mma16(c[mi][nj], ah0, ah1, ah2, ah3, Bh[nj][0], Bh[nj][1]);
            }
        }
    }

    // epilogue
#pragma unroll
    for (int mi = 0; mi < 4; mi++) {
        int r0 = m0 + wm * 64 + mi * 16 + g;
        int r1 = r0 + 8;
#pragma unroll
        for (int nj = 0; nj < 4; nj++) {
            int col = n0 + wn * 32 + nj * 8 + 2 * t4;
            float bb0 = bias[col], bb1 = bias[col + 1];
            float v00 = c[mi][nj][0] + bb0, v01 = c[mi][nj][1] + bb1;
            float v10 = c[mi][nj][2] + bb0, v11 = c[mi][nj][3] + bb1;
            if (mode == 3) {
                *(float2*)&outp[(size_t)r0 * EMBED + col] = make_float2(v00, v01);
                *(float2*)&outp[(size_t)r1 * EMBED + col] = make_float2(v10, v11);
            } else {
                int h  = col >> 6, dh = col & 63;
                int b0i = r0 >> 11, s0i = r0 & 2047;
                int b1i = r1 >> 11, s1i = r1 & 2047;
                size_t o0 = (((size_t)(b0i * NHEAD + h)) * SEQ + s0i) * HDIM + dh;
                size_t o1 = (((size_t)(b1i * NHEAD + h)) * SEQ + s1i) * HDIM + dh;
                if (mode == 0) {
                    *(float2*)&g_q[o0] = make_float2(v00, v01);
                    *(float2*)&g_q[o1] = make_float2(v10, v11);
                } else if (mode == 1) {
                    store_split2(g_k_hi, g_k_lo, o0, v00, v01);
                    store_split2(g_k_hi, g_k_lo, o1, v10, v11);
                } else {
                    store_split2(g_v_hi, g_v_lo, o0, v00, v01);
                    store_split2(g_v_hi, g_v_lo, o1, v10, v11);
                }
            }
        }
    }
}

// ---------------------------------------------------------------------------
// Flash attention (bf16x3, EXACT R7 version): AQ=128 (8 warps x 16 rows), BK=32,
// cp.async double-buffered pre-split K/V, in-register online softmax,
// P staged via smem (16 fp32 regs for S => no spills; regs=126).
// ---------------------------------------------------------------------------
#define AQ  128
#define AK  32
#define NIT (SEQ / AK)   /* 64 */
#define QST 72
#define PST 40
#define KST 72
#define VST 72

#define OQH 0
#define OQL 18432
#define OPH 36864
#define OPL 47104
#define OKH 57344
#define OKL 66560
#define OVH 75776
#define OVL 84992
#define OMK 94208
#define ATTN_SMEM_B 94464
#define KBUF 4608

__global__ __launch_bounds__(256, 2) void attn_bf16(const int* __restrict__ mask)
{
    extern __shared__ char smraw[];
    const uint32_t sm_u = s2u(smraw);

    __nv_bfloat16* Qh = (__nv_bfloat16*)(smraw + OQH);
    __nv_bfloat16* Ql = (__nv_bfloat16*)(smraw + OQL);
    __nv_bfloat16* Ph = (__nv_bfloat16*)(smraw + OPH);
    __nv_bfloat16* Pl = (__nv_bfloat16*)(smraw + OPL);
    int* mks = (int*)(smraw + OMK);

    const int t    = threadIdx.x;
    const int lane = t & 31;
    const int w    = t >> 5;
    const int bh   = blockIdx.y;
    const int b    = bh >> 4;
    const int h    = bh & 15;
    const int q0   = blockIdx.x * AQ;

    const int t4    = lane & 3;
    const int g     = lane >> 2;
    const int l15   = lane & 15;
    const int row_l = (lane & 7) + ((lane >> 3) & 1) * 8;
    const int khalf = lane >> 4;

    const float* Qg = g_q + (size_t)bh * SEQ * HDIM;
    const __nv_bfloat16* Kgh = g_k_hi + (size_t)bh * SEQ * HDIM;
    const __nv_bfloat16* Kgl = g_k_lo + (size_t)bh * SEQ * HDIM;
    const __nv_bfloat16* Vgh = g_v_hi + (size_t)bh * SEQ * HDIM;
    const __nv_bfloat16* Vgl = g_v_lo + (size_t)bh * SEQ * HDIM;

    const int crow = t >> 3, cseg = t & 7;
    const uint32_t csoff = (uint32_t)((crow * KST + cseg * 8) * 2);
    const size_t   cgbase = (size_t)crow * HDIM + cseg * 8;

    const uint32_t qah = sm_u + OQH + (uint32_t)(((w * 16 + row_l) * QST + khalf * 8) * 2);
    const uint32_t qal = sm_u + OQL + (uint32_t)(((w * 16 + row_l) * QST + khalf * 8) * 2);
    const uint32_t pah = sm_u + OPH + (uint32_t)(((w * 16 + row_l) * PST + khalf * 8) * 2);
    const uint32_t pal = sm_u + OPL + (uint32_t)(((w * 16 + row_l) * PST + khalf * 8) * 2);
    const uint32_t kboff = (uint32_t)(((l15 & 7) * KST + (l15 >> 3) * 8) * 2);
    const uint32_t vboff = (uint32_t)((((l15 & 7) + 8 * (l15 >> 3)) * VST) * 2);

    cp16(sm_u + OKH + csoff, Kgh + cgbase);
    cp16(sm_u + OKL + csoff, Kgl + cgbase);
    cp16(sm_u + OVH + csoff, Vgh + cgbase);
    cp16(sm_u + OVL + csoff, Vgl + cgbase);
    if (t < 8) cp16(sm_u + OMK + t * 16, mask + b * SEQ + t * 4);
    CP_COMMIT();

#pragma unroll
    for (int l = 0; l < 8; l++) {
        int e = l * 256 + t, row = e >> 4, seg = e & 15;
        float4 v = *(const float4*)&Qg[(size_t)(q0 + row) * HDIM + seg * 4];
        v.x *= 0.125f; v.y *= 0.125f; v.z *= 0.125f; v.w *= 0.125f;
        __nv_bfloat162 h01, h23, l01, l23;
        split4(v, h01, h23, l01, l23);
        int off = row * QST + seg * 4;
        *(__nv_bfloat162*)&Qh[off]     = h01;
        *(__nv_bfloat162*)&Qh[off + 2] = h23;
        *(__nv_bfloat162*)&Ql[off]     = l01;
        *(__nv_bfloat162*)&Ql[off + 2] = l23;
    }

    float o[8][4];
#pragma unroll
    for (int j = 0; j < 8; j++)
#pragma unroll
        for (int i = 0; i < 4; i++) o[j][i] = 0.f;
    float m0 = -1e30f, m1 = -1e30f, l0 = 0.f, l1 = 0.f;

    __syncthreads();

    for (int it = 0; it < NIT; it++) {
        const int buf = it & 1;
        if (it + 1 < NIT) {
            const int nb = buf ^ 1;
            const size_t gb = cgbase + (size_t)(it + 1) * AK * HDIM;
            const uint32_t so = (uint32_t)(nb * KBUF) + csoff;
            cp16(sm_u + OKH + so, Kgh + gb);
            cp16(sm_u + OKL + so, Kgl + gb);
            cp16(sm_u + OVH + so, Vgh + gb);
            cp16(sm_u + OVL + so, Vgl + gb);
            if (t < 8) cp16(sm_u + OMK + (uint32_t)(nb * 128 + t * 16),
                            mask + b * SEQ + (it + 1) * AK + t * 4);
            CP_COMMIT();
            CP_WAIT1();
        } else {
            CP_WAIT0();
        }
        __syncthreads();

        const uint32_t khb = sm_u + OKH + (uint32_t)(buf * KBUF) + kboff;
        const uint32_t klb = sm_u + OKL + (uint32_t)(buf * KBUF) + kboff;
        const uint32_t vhb = sm_u + OVH + (uint32_t)(buf * KBUF) + vboff;
        const uint32_t vlb = sm_u + OVL + (uint32_t)(buf * KBUF) + vboff;
        const int* mk = mks + buf * 32;

        float s[4][4];
#pragma unroll
        for (int j = 0; j < 4; j++)
#pragma unroll
            for (int i = 0; i < 4; i++) s[j][i] = 0.f;

#pragma unroll
        for (int ks = 0; ks < 4; ks++) {
            uint32_t ah0, ah1, ah2, ah3, al0, al1, al2, al3;
            ldm_x4(ah0, ah1, ah2, ah3, qah + (uint32_t)(ks * 32));
            ldm_x4(al0, al1, al2, al3, qal + (uint32_t)(ks * 32));
#pragma unroll
            for (int j = 0; j < 4; j++) {
                uint32_t bh0, bh1, bl0, bl1;
                uint32_t off = (uint32_t)(j * 8 * KST * 2 + ks * 32);
                ldm_x2(bh0, bh1, khb + off);
                ldm_x2(bl0, bl1, klb + off);
                mma16(s[j], al0, al1, al2, al3, bh0, bh1);
                mma16(s[j], ah0, ah1, ah2, ah3, bl0, bl1);
                mma16(s[j], ah0, ah1, ah2, ah3, bh0, bh1);
            }
        }

        float mx0 = -1e30f, mx1 = -1e30f;
#pragma unroll
        for (int j = 0; j < 4; j++) {
            int cb = j * 8 + 2 * t4;
            if (mk[cb] == 0)     { s[j][0] = -1e9f; s[j][2] = -1e9f; }
            if (mk[cb + 1] == 0) { s[j][1] = -1e9f; s[j][3] = -1e9f; }
            mx0 = fmaxf(mx0, fmaxf(s[j][0], s[j][1]));
            mx1 = fmaxf(mx1, fmaxf(s[j][2], s[j][3]));
        }
        mx0 = fmaxf(mx0, __shfl_xor_sync(0xffffffffu, mx0, 1));
        mx0 = fmaxf(mx0, __shfl_xor_sync(0xffffffffu, mx0, 2));
        mx1 = fmaxf(mx1, __shfl_xor_sync(0xffffffffu, mx1, 1));
        mx1 = fmaxf(mx1, __shfl_xor_sync(0xffffffffu, mx1, 2));

        float mn0 = fmaxf(m0, mx0), mn1 = fmaxf(m1, mx1);
        float f0 = __expf(m0 - mn0), f1 = __expf(m1 - mn1);
        m0 = mn0; m1 = mn1;

        float sum0 = 0.f, sum1 = 0.f;
        int pr0 = (w * 16 + g) * PST;
        int pr1 = (w * 16 + g + 8) * PST;
#pragma unroll
        for (int j = 0; j < 4; j++) {
            int cb = j * 8 + 2 * t4;
            float p00 = __expf(s[j][0] - m0);
            float p01 = __expf(s[j][1] - m0);
            float p10 = __expf(s[j][2] - m1);
            float p11 = __expf(s[j][3] - m1);
            sum0 += p00 + p01;
            sum1 += p10 + p11;
            __nv_bfloat162 h0 = __floats2bfloat162_rn(p00, p01);
            __nv_bfloat162 h1 = __floats2bfloat162_rn(p10, p11);
            float2 hf0 = __bfloat1622float2(h0);
            float2 hf1 = __bfloat1622float2(h1);
            *(__nv_bfloat162*)&Ph[pr0 + cb] = h0;
            *(__nv_bfloat162*)&Ph[pr1 + cb] = h1;
            *(__nv_bfloat162*)&Pl[pr0 + cb] = __floats2bfloat162_rn(p00 - hf0.x, p01 - hf0.y);
            *(__nv_bfloat162*)&Pl[pr1 + cb] = __floats2bfloat162_rn(p10 - hf1.x, p11 - hf1.y);
        }
        sum0 += __shfl_xor_sync(0xffffffffu, sum0, 1);
        sum0 += __shfl_xor_sync(0xffffffffu, sum0, 2);
        sum1 += __shfl_xor_sync(0xffffffffu, sum1, 1);
        sum1 += __shfl_xor_sync(0xffffffffu, sum1, 2);
        l0 = l0 * f0 + sum0;
        l1 = l1 * f1 + sum1;

#pragma unroll
        for (int j = 0; j < 8; j++) {
            o[j][0] *= f0; o[j][1] *= f0; o[j][2] *= f1; o[j][3] *= f1;
        }
        __syncwarp();

#pragma unroll
        for (int ks = 0; ks < 2; ks++) {
            uint32_t ph0, ph1, ph2, ph3, pl0, pl1, pl2, pl3;
            ldm_x4(ph0, ph1, ph2, ph3, pah + (uint32_t)(ks * 32));
            ldm_x4(pl0, pl1, pl2, pl3, pal + (uint32_t)(ks * 32));
#pragma unroll
            for (int j = 0; j < 8; j++) {
                uint32_t vh0, vh1, vl0, vl1;
                uint32_t off = (uint32_t)(ks * 16 * VST * 2 + j * 16);
                ldmT_x2(vh0, vh1, vhb + off);
                ldmT_x2(vl0, vl1, vlb + off);
                mma16(o[j], pl0, pl1, pl2, pl3, vh0, vh1);
                mma16(o[j], ph0, ph1, ph2, ph3, vl0, vl1);
                mma16(o[j], ph0, ph1, ph2, ph3, vh0, vh1);
            }
        }
        __syncthreads();
    }

    float il0 = 1.f / l0, il1 = 1.f / l1;
    size_t base0 = ((size_t)b * SEQ + q0 + w * 16 + g) * EMBED + h * HDIM;
    size_t base1 = base0 + (size_t)8 * EMBED;
#pragma unroll
    for (int j = 0; j < 8; j++) {
        int col = j * 8 + 2 * t4;
        *(float2*)&g_attn[base0 + col] = make_float2(o[j][0] * il0, o[j][1] * il0);
        *(float2*)&g_attn[base1 + col] = make_float2(o[j][2] * il1, o[j][3] * il1);
    }
}

// ---------------------------------------------------------------------------
extern "C" void kernel_launch(void* const* d_in, const int* in_sizes, int n_in,
                              void* d_out, int out_size)
{
    const float* x    = (const float*)d_in[0];
    const int*   mask = (const int*)  d_in[1];
    const float* Wq   = (const float*)d_in[2];
    const float* bq   = (const float*)d_in[3];
    const float* Wk   = (const float*)d_in[4];
    const float* bk   = (const float*)d_in[5];
    const float* Wv   = (const float*)d_in[6];
    const float* bv   = (const float*)d_in[7];
    const float* Wo   = (const float*)d_in[8];
    const float* bo   = (const float*)d_in[9];
    float* out = (float*)d_out;

    cudaFuncSetAttribute(attn_bf16,
                         cudaFuncAttributeMaxDynamicSharedMemorySize, ATTN_SMEM_B);
    cudaFuncSetAttribute(gemm_ms,
                         cudaFuncAttributeMaxDynamicSharedMemorySize, GEMM_SMEM);

    const int NX4 = MTOT * EMBED / 4;    // 1,048,576
    const int NW4 = EMBED * EMBED / 4;   //   262,144

    split_f32<<<(NX4 + 255) / 256, 256>>>((const float4*)x,  0, NX4);
    split_f32<<<(NW4 + 255) / 256, 256>>>((const float4*)Wq, 1, NW4);
    split_f32<<<(NW4 + 255) / 256, 256>>>((const float4*)Wk, 2, NW4);
    split_f32<<<(NW4 + 255) / 256, 256>>>((const float4*)Wv, 3, NW4);
    split_f32<<<(NW4 + 255) / 256, 256>>>((const float4*)Wo, 4, NW4);

    dim3 gg(EMBED / 128, MTOT / 128);    // (8, 32) = 256 CTAs
    gemm_ms<<<gg, 256, GEMM_SMEM>>>(bq, nullptr, 0);
    gemm_ms<<<gg, 256, GEMM_SMEM>>>(bk, nullptr, 1);
    gemm_ms<<<gg, 256, GEMM_SMEM>>>(bv, nullptr, 2);

    attn_bf16<<<dim3(SEQ / AQ, BATCH * NHEAD), 256, ATTN_SMEM_B>>>(mask);

    split_f32<<<(NX4 + 255) / 256, 256>>>(nullptr, 5, NX4);
    gemm_ms<<<gg, 256, GEMM_SMEM>>>(bo, out, 3);
}

// round 13
// speedup vs baseline: 1.6326x; 1.0991x over previous
#include <cuda_runtime.h>
#include <cuda_bf16.h>
#include <cstdint>

#define EMBED 1024
#define NHEAD 16
#define HDIM  64
#define BATCH 2
#define SEQ   2048
#define MTOT  (BATCH*SEQ)   /* 4096 */

// Scratch (device globals: allocation-free per harness rules)
__device__ float g_q[MTOT*EMBED];            // fp32, [B,H,S,Dh]
__device__ float g_attn[MTOT*EMBED];         // fp32, [B,S,E]
__device__ __nv_bfloat16 g_k_hi[MTOT*EMBED]; // bf16 split, [B,H,S,Dh]
__device__ __nv_bfloat16 g_k_lo[MTOT*EMBED];
__device__ __nv_bfloat16 g_v_hi[MTOT*EMBED];
__device__ __nv_bfloat16 g_v_lo[MTOT*EMBED];

// ---------------------------------------------------------------------------
// helpers
// ---------------------------------------------------------------------------
__device__ __forceinline__ uint32_t s2u(const void* p) {
    return (uint32_t)__cvta_generic_to_shared(p);
}
__device__ __forceinline__ void ldm_x4(uint32_t& r0, uint32_t& r1, uint32_t& r2,
                                       uint32_t& r3, uint32_t addr) {
    asm volatile("ldmatrix.sync.aligned.m8n8.x4.shared.b16 {%0,%1,%2,%3}, [%4];"
                 : "=r"(r0), "=r"(r1), "=r"(r2), "=r"(r3) : "r"(addr));
}
__device__ __forceinline__ void ldm_x2(uint32_t& r0, uint32_t& r1, uint32_t addr) {
    asm volatile("ldmatrix.sync.aligned.m8n8.x2.shared.b16 {%0,%1}, [%2];"
                 : "=r"(r0), "=r"(r1) : "r"(addr));
}
__device__ __forceinline__ void ldmT_x2(uint32_t& r0, uint32_t& r1, uint32_t addr) {
    asm volatile("ldmatrix.sync.aligned.m8n8.x2.trans.shared.b16 {%0,%1}, [%2];"
                 : "=r"(r0), "=r"(r1) : "r"(addr));
}
__device__ __forceinline__ void mma16(float* c, uint32_t a0, uint32_t a1,
                                      uint32_t a2, uint32_t a3,
                                      uint32_t b0, uint32_t b1) {
    asm volatile(
        "mma.sync.aligned.m16n8k16.row.col.f32.bf16.bf16.f32 "
        "{%0,%1,%2,%3}, {%4,%5,%6,%7}, {%8,%9}, {%0,%1,%2,%3};"
        : "+f"(c[0]), "+f"(c[1]), "+f"(c[2]), "+f"(c[3])
        : "r"(a0), "r"(a1), "r"(a2), "r"(a3), "r"(b0), "r"(b1));
}
__device__ __forceinline__ void cp16(uint32_t dst, const void* src) {
    asm volatile("cp.async.cg.shared.global [%0], [%1], 16;" :: "r"(dst), "l"(src));
}
#define CP_COMMIT() asm volatile("cp.async.commit_group;")
#define CP_WAIT0()  asm volatile("cp.async.wait_group 0;")
#define CP_WAIT1()  asm volatile("cp.async.wait_group 1;")

// split fp32x4 -> (hi bf16x2 pair, lo bf16x2 pair)
__device__ __forceinline__ void split4(float4 v,
        __nv_bfloat162& h01, __nv_bfloat162& h23,
        __nv_bfloat162& l01, __nv_bfloat162& l23) {
    h01 = __floats2bfloat162_rn(v.x, v.y);
    h23 = __floats2bfloat162_rn(v.z, v.w);
    float2 f01 = __bfloat1622float2(h01);
    float2 f23 = __bfloat1622float2(h23);
    l01 = __floats2bfloat162_rn(v.x - f01.x, v.y - f01.y);
    l23 = __floats2bfloat162_rn(v.z - f23.x, v.w - f23.y);
}
__device__ __forceinline__ void store_split2(__nv_bfloat16* ph, __nv_bfloat16* pl,
                                             size_t off, float x, float y) {
    __nv_bfloat162 h = __floats2bfloat162_rn(x, y);
    float2 hf = __bfloat1622float2(h);
    __nv_bfloat162 l = __floats2bfloat162_rn(x - hf.x, y - hf.y);
    *(__nv_bfloat162*)&ph[off] = h;
    *(__nv_bfloat162*)&pl[off] = l;
}

// ---------------------------------------------------------------------------
// GEMM (bf16x3, inline split, double-buffered smem): C = A @ W^T + bias
// 128x128 tile, kc=16, 2-stage smem, ONE barrier per chunk, 256 threads.
// mode 0: A=x -> g_q fp32 [B,H,S,Dh];  1: -> g_k hi/lo;  2: -> g_v hi/lo;
// mode 3: A=g_attn -> Oout fp32 [M,N]
// ---------------------------------------------------------------------------
#define GST 24                   /* smem k-stride in bf16 elems (16 + 8 pad) */
#define TSZb (128 * GST * 2)     /* 6144 B per tensor */
#define STGb (4 * TSZb)          /* 24576 B per stage: Ah, Al, Bh, Bl */
#define GEMM_SMEM (2 * STGb)     /* 49152 B */
#define NCHUNK 64

__global__ __launch_bounds__(256, 2) void gemm_db(
    const float* __restrict__ Ain, const float* __restrict__ W,
    const float* __restrict__ bias, float* __restrict__ Oout, int mode)
{
    extern __shared__ char gsm[];
    const uint32_t smu = s2u(gsm);

    const float* A = (mode == 3) ? g_attn : Ain;

    const int t    = threadIdx.x;
    const int lane = t & 31;
    const int w    = t >> 5;
    const int wm   = w >> 2;        // 0..1  (64 rows each)
    const int wn   = w & 3;         // 0..3  (32 cols each)
    const int m0   = blockIdx.y * 128;
    const int n0   = blockIdx.x * 128;

    const int t4    = lane & 3;
    const int g     = lane >> 2;
    const int l15   = lane & 15;
    const int row_l = (lane & 7) + ((lane >> 3) & 1) * 8;
    const int khalf = lane >> 4;

    const uint32_t a_off = (uint32_t)(((wm * 64 + row_l) * GST + khalf * 8) * 2);
    const uint32_t b_off = (uint32_t)(((wn * 32 + (l15 & 7)) * GST + (l15 >> 3) * 8) * 2);

    float c[4][4][4];
#pragma unroll
    for (int mi = 0; mi < 4; mi++)
#pragma unroll
        for (int nj = 0; nj < 4; nj++)
#pragma unroll
            for (int i = 0; i < 4; i++) c[mi][nj][i] = 0.f;

    // chunk-load indices: 512 float4 per matrix per chunk, 2 per thread
    const int r0g = (0 * 256 + t) >> 2, s0g = (0 * 256 + t) & 3;
    const int r1g = (1 * 256 + t) >> 2, s1g = (1 * 256 + t) & 3;

    float4 av0, av1, bv0, bv1;

    auto ldg_chunk = [&](int kb) {
        const int k0 = kb * 16;
        av0 = *(const float4*)&A[(size_t)(m0 + r0g) * EMBED + k0 + s0g * 4];
        av1 = *(const float4*)&A[(size_t)(m0 + r1g) * EMBED + k0 + s1g * 4];
        bv0 = *(const float4*)&W[(size_t)(n0 + r0g) * EMBED + k0 + s0g * 4];
        bv1 = *(const float4*)&W[(size_t)(n0 + r1g) * EMBED + k0 + s1g * 4];
    };

    auto sts_chunk = [&](int stage) {
        char* base = gsm + stage * STGb;
        __nv_bfloat16* Ash = (__nv_bfloat16*)(base);
        __nv_bfloat16* Asl = (__nv_bfloat16*)(base + TSZb);
        __nv_bfloat16* Bsh = (__nv_bfloat16*)(base + 2 * TSZb);
        __nv_bfloat16* Bsl = (__nv_bfloat16*)(base + 3 * TSZb);
        __nv_bfloat162 h01, h23, l01, l23;
        split4(av0, h01, h23, l01, l23);
        *(__nv_bfloat162*)&Ash[r0g * GST + s0g * 4]     = h01;
        *(__nv_bfloat162*)&Ash[r0g * GST + s0g * 4 + 2] = h23;
        *(__nv_bfloat162*)&Asl[r0g * GST + s0g * 4]     = l01;
        *(__nv_bfloat162*)&Asl[r0g * GST + s0g * 4 + 2] = l23;
        split4(av1, h01, h23, l01, l23);
        *(__nv_bfloat162*)&Ash[r1g * GST + s1g * 4]     = h01;
        *(__nv_bfloat162*)&Ash[r1g * GST + s1g * 4 + 2] = h23;
        *(__nv_bfloat162*)&Asl[r1g * GST + s1g * 4]     = l01;
        *(__nv_bfloat162*)&Asl[r1g * GST + s1g * 4 + 2] = l23;
        split4(bv0, h01, h23, l01, l23);
        *(__nv_bfloat162*)&Bsh[r0g * GST + s0g * 4]     = h01;
        *(__nv_bfloat162*)&Bsh[r0g * GST + s0g * 4 + 2] = h23;
        *(__nv_bfloat162*)&Bsl[r0g * GST + s0g * 4]     = l01;
        *(__nv_bfloat162*)&Bsl[r0g * GST + s0g * 4 + 2] = l23;
        split4(bv1, h01, h23, l01, l23);
        *(__nv_bfloat162*)&Bsh[r1g * GST + s1g * 4]     = h01;
        *(__nv_bfloat162*)&Bsh[r1g * GST + s1g * 4 + 2] = h23;
        *(__nv_bfloat162*)&Bsl[r1g * GST + s1g * 4]     = l01;
        *(__nv_bfloat162*)&Bsl[r1g * GST + s1g * 4 + 2] = l23;
    };

    // prologue: chunk0 -> stage0; prefetch chunk1 into regs
    ldg_chunk(0);
    sts_chunk(0);
    ldg_chunk(1);
    __syncthreads();

    for (int kb = 0; kb < NCHUNK; kb++) {
        const uint32_t sb = smu + (uint32_t)((kb & 1) * STGb);

        // MMA on stage kb&1
        uint32_t Bh[4][2], Bl[4][2];
#pragma unroll
        for (int nj = 0; nj < 4; nj++) {
            ldm_x2(Bh[nj][0], Bh[nj][1], sb + 2 * TSZb + b_off + (uint32_t)(nj * 8 * GST * 2));
            ldm_x2(Bl[nj][0], Bl[nj][1], sb + 3 * TSZb + b_off + (uint32_t)(nj * 8 * GST * 2));
        }
#pragma unroll
        for (int mi = 0; mi < 4; mi++) {
            uint32_t ah0, ah1, ah2, ah3, al0, al1, al2, al3;
            uint32_t ao = a_off + (uint32_t)(mi * 16 * GST * 2);
            ldm_x4(ah0, ah1, ah2, ah3, sb + ao);
            ldm_x4(al0, al1, al2, al3, sb + TSZb + ao);
#pragma unroll
            for (int nj = 0; nj < 4; nj++) {
                mma16(c[mi][nj], al0, al1, al2, al3, Bh[nj][0], Bh[nj][1]);
                mma16(c[mi][nj], ah0, ah1, ah2, ah3, Bl[nj][0], Bl[nj][1]);
                mma16(c[mi][nj], ah0, ah1, ah2, ah3, Bh[nj][0], Bh[nj][1]);
            }
        }

        // stage kb+1: split regs -> other buffer; prefetch kb+2; single barrier
        if (kb + 1 < NCHUNK) {
            sts_chunk((kb + 1) & 1);
            if (kb + 2 < NCHUNK) ldg_chunk(kb + 2);
            __syncthreads();
        }
    }

    // epilogue
#pragma unroll
    for (int mi = 0; mi < 4; mi++) {
        int r0 = m0 + wm * 64 + mi * 16 + g;
        int r1 = r0 + 8;
#pragma unroll
        for (int nj = 0; nj < 4; nj++) {
            int col = n0 + wn * 32 + nj * 8 + 2 * t4;
            float bb0 = bias[col], bb1 = bias[col + 1];
            float v00 = c[mi][nj][0] + bb0, v01 = c[mi][nj][1] + bb1;
            float v10 = c[mi][nj][2] + bb0, v11 = c[mi][nj][3] + bb1;
            if (mode == 3) {
                *(float2*)&Oout[(size_t)r0 * EMBED + col] = make_float2(v00, v01);
                *(float2*)&Oout[(size_t)r1 * EMBED + col] = make_float2(v10, v11);
            } else {
                int h  = col >> 6, dh = col & 63;
                int b0i = r0 >> 11, s0i = r0 & 2047;
                int b1i = r1 >> 11, s1i = r1 & 2047;
                size_t o0 = (((size_t)(b0i * NHEAD + h)) * SEQ + s0i) * HDIM + dh;
                size_t o1 = (((size_t)(b1i * NHEAD + h)) * SEQ + s1i) * HDIM + dh;
                if (mode == 0) {
                    *(float2*)&g_q[o0] = make_float2(v00, v01);
                    *(float2*)&g_q[o1] = make_float2(v10, v11);
                } else if (mode == 1) {
                    store_split2(g_k_hi, g_k_lo, o0, v00, v01);
                    store_split2(g_k_hi, g_k_lo, o1, v10, v11);
                } else {
                    store_split2(g_v_hi, g_v_lo, o0, v00, v01);
                    store_split2(g_v_hi, g_v_lo, o1, v10, v11);
                }
            }
        }
    }
}

// ---------------------------------------------------------------------------
// Flash attention (bf16x3, EXACT R7 version): AQ=128 (8 warps x 16 rows), BK=32,
// cp.async double-buffered pre-split K/V, in-register online softmax,
// P staged via smem (regs=126, no spills).
// ---------------------------------------------------------------------------
#define AQ  128
#define AK  32
#define NIT (SEQ / AK)   /* 64 */
#define QST 72
#define PST 40
#define KST 72
#define VST 72

#define OQH 0
#define OQL 18432
#define OPH 36864
#define OPL 47104
#define OKH 57344
#define OKL 66560
#define OVH 75776
#define OVL 84992
#define OMK 94208
#define ATTN_SMEM_B 94464
#define KBUF 4608

__global__ __launch_bounds__(256, 2) void attn_bf16(const int* __restrict__ mask)
{
    extern __shared__ char smraw[];
    const uint32_t sm_u = s2u(smraw);

    __nv_bfloat16* Qh = (__nv_bfloat16*)(smraw + OQH);
    __nv_bfloat16* Ql = (__nv_bfloat16*)(smraw + OQL);
    __nv_bfloat16* Ph = (__nv_bfloat16*)(smraw + OPH);
    __nv_bfloat16* Pl = (__nv_bfloat16*)(smraw + OPL);
    int* mks = (int*)(smraw + OMK);

    const int t    = threadIdx.x;
    const int lane = t & 31;
    const int w    = t >> 5;
    const int bh   = blockIdx.y;
    const int b    = bh >> 4;
    const int h    = bh & 15;
    const int q0   = blockIdx.x * AQ;

    const int t4    = lane & 3;
    const int g     = lane >> 2;
    const int l15   = lane & 15;
    const int row_l = (lane & 7) + ((lane >> 3) & 1) * 8;
    const int khalf = lane >> 4;

    const float* Qg = g_q + (size_t)bh * SEQ * HDIM;
    const __nv_bfloat16* Kgh = g_k_hi + (size_t)bh * SEQ * HDIM;
    const __nv_bfloat16* Kgl = g_k_lo + (size_t)bh * SEQ * HDIM;
    const __nv_bfloat16* Vgh = g_v_hi + (size_t)bh * SEQ * HDIM;
    const __nv_bfloat16* Vgl = g_v_lo + (size_t)bh * SEQ * HDIM;

    const int crow = t >> 3, cseg = t & 7;
    const uint32_t csoff = (uint32_t)((crow * KST + cseg * 8) * 2);
    const size_t   cgbase = (size_t)crow * HDIM + cseg * 8;

    const uint32_t qah = sm_u + OQH + (uint32_t)(((w * 16 + row_l) * QST + khalf * 8) * 2);
    const uint32_t qal = sm_u + OQL + (uint32_t)(((w * 16 + row_l) * QST + khalf * 8) * 2);
    const uint32_t pah = sm_u + OPH + (uint32_t)(((w * 16 + row_l) * PST + khalf * 8) * 2);
    const uint32_t pal = sm_u + OPL + (uint32_t)(((w * 16 + row_l) * PST + khalf * 8) * 2);
    const uint32_t kboff = (uint32_t)(((l15 & 7) * KST + (l15 >> 3) * 8) * 2);
    const uint32_t vboff = (uint32_t)((((l15 & 7) + 8 * (l15 >> 3)) * VST) * 2);

    cp16(sm_u + OKH + csoff, Kgh + cgbase);
    cp16(sm_u + OKL + csoff, Kgl + cgbase);
    cp16(sm_u + OVH + csoff, Vgh + cgbase);
    cp16(sm_u + OVL + csoff, Vgl + cgbase);
    if (t < 8) cp16(sm_u + OMK + t * 16, mask + b * SEQ + t * 4);
    CP_COMMIT();

#pragma unroll
    for (int l = 0; l < 8; l++) {
        int e = l * 256 + t, row = e >> 4, seg = e & 15;
        float4 v = *(const float4*)&Qg[(size_t)(q0 + row) * HDIM + seg * 4];
        v.x *= 0.125f; v.y *= 0.125f; v.z *= 0.125f; v.w *= 0.125f;
        __nv_bfloat162 h01, h23, l01, l23;
        split4(v, h01, h23, l01, l23);
        int off = row * QST + seg * 4;
        *(__nv_bfloat162*)&Qh[off]     = h01;
        *(__nv_bfloat162*)&Qh[off + 2] = h23;
        *(__nv_bfloat162*)&Ql[off]     = l01;
        *(__nv_bfloat162*)&Ql[off + 2] = l23;
    }

    float o[8][4];
#pragma unroll
    for (int j = 0; j < 8; j++)
#pragma unroll
        for (int i = 0; i < 4; i++) o[j][i] = 0.f;
    float m0 = -1e30f, m1 = -1e30f, l0 = 0.f, l1 = 0.f;

    __syncthreads();

    for (int it = 0; it < NIT; it++) {
        const int buf = it & 1;
        if (it + 1 < NIT) {
            const int nb = buf ^ 1;
            const size_t gb = cgbase + (size_t)(it + 1) * AK * HDIM;
            const uint32_t so = (uint32_t)(nb * KBUF) + csoff;
            cp16(sm_u + OKH + so, Kgh + gb);
            cp16(sm_u + OKL + so, Kgl + gb);
            cp16(sm_u + OVH + so, Vgh + gb);
            cp16(sm_u + OVL + so, Vgl + gb);
            if (t < 8) cp16(sm_u + OMK + (uint32_t)(nb * 128 + t * 16),
                            mask + b * SEQ + (it + 1) * AK + t * 4);
            CP_COMMIT();
            CP_WAIT1();
        } else {
            CP_WAIT0();
        }
        __syncthreads();

        const uint32_t khb = sm_u + OKH + (uint32_t)(buf * KBUF) + kboff;
        const uint32_t klb = sm_u + OKL + (uint32_t)(buf * KBUF) + kboff;
        const uint32_t vhb = sm_u + OVH + (uint32_t)(buf * KBUF) + vboff;
        const uint32_t vlb = sm_u + OVL + (uint32_t)(buf * KBUF) + vboff;
        const int* mk = mks + buf * 32;

        float s[4][4];
#pragma unroll
        for (int j = 0; j < 4; j++)
#pragma unroll
            for (int i = 0; i < 4; i++) s[j][i] = 0.f;

#pragma unroll
        for (int ks = 0; ks < 4; ks++) {
            uint32_t ah0, ah1, ah2, ah3, al0, al1, al2, al3;
            ldm_x4(ah0, ah1, ah2, ah3, qah + (uint32_t)(ks * 32));
            ldm_x4(al0, al1, al2, al3, qal + (uint32_t)(ks * 32));
#pragma unroll
            for (int j = 0; j < 4; j++) {
                uint32_t bh0, bh1, bl0, bl1;
                uint32_t off = (uint32_t)(j * 8 * KST * 2 + ks * 32);
                ldm_x2(bh0, bh1, khb + off);
                ldm_x2(bl0, bl1, klb + off);
                mma16(s[j], al0, al1, al2, al3, bh0, bh1);
                mma16(s[j], ah0, ah1, ah2, ah3, bl0, bl1);
                mma16(s[j], ah0, ah1, ah2, ah3, bh0, bh1);
            }
        }

        float mx0 = -1e30f, mx1 = -1e30f;
#pragma unroll
        for (int j = 0; j < 4; j++) {
            int cb = j * 8 + 2 * t4;
            if (mk[cb] == 0)     { s[j][0] = -1e9f; s[j][2] = -1e9f; }
            if (mk[cb + 1] == 0) { s[j][1] = -1e9f; s[j][3] = -1e9f; }
            mx0 = fmaxf(mx0, fmaxf(s[j][0], s[j][1]));
            mx1 = fmaxf(mx1, fmaxf(s[j][2], s[j][3]));
        }
        mx0 = fmaxf(mx0, __shfl_xor_sync(0xffffffffu, mx0, 1));
        mx0 = fmaxf(mx0, __shfl_xor_sync(0xffffffffu, mx0, 2));
        mx1 = fmaxf(mx1, __shfl_xor_sync(0xffffffffu, mx1, 1));
        mx1 = fmaxf(mx1, __shfl_xor_sync(0xffffffffu, mx1, 2));

        float mn0 = fmaxf(m0, mx0), mn1 = fmaxf(m1, mx1);
        float f0 = __expf(m0 - mn0), f1 = __expf(m1 - mn1);
        m0 = mn0; m1 = mn1;

        float sum0 = 0.f, sum1 = 0.f;
        int pr0 = (w * 16 + g) * PST;
        int pr1 = (w * 16 + g + 8) * PST;
#pragma unroll
        for (int j = 0; j < 4; j++) {
            int cb = j * 8 + 2 * t4;
            float p00 = __expf(s[j][0] - m0);
            float p01 = __expf(s[j][1] - m0);
            float p10 = __expf(s[j][2] - m1);
            float p11 = __expf(s[j][3] - m1);
            sum0 += p00 + p01;
            sum1 += p10 + p11;
            __nv_bfloat162 h0 = __floats2bfloat162_rn(p00, p01);
            __nv_bfloat162 h1 = __floats2bfloat162_rn(p10, p11);
            float2 hf0 = __bfloat1622float2(h0);
            float2 hf1 = __bfloat1622float2(h1);
            *(__nv_bfloat162*)&Ph[pr0 + cb] = h0;
            *(__nv_bfloat162*)&Ph[pr1 + cb] = h1;
            *(__nv_bfloat162*)&Pl[pr0 + cb] = __floats2bfloat162_rn(p00 - hf0.x, p01 - hf0.y);
            *(__nv_bfloat162*)&Pl[pr1 + cb] = __floats2bfloat162_rn(p10 - hf1.x, p11 - hf1.y);
        }
        sum0 += __shfl_xor_sync(0xffffffffu, sum0, 1);
        sum0 += __shfl_xor_sync(0xffffffffu, sum0, 2);
        sum1 += __shfl_xor_sync(0xffffffffu, sum1, 1);
        sum1 += __shfl_xor_sync(0xffffffffu, sum1, 2);
        l0 = l0 * f0 + sum0;
        l1 = l1 * f1 + sum1;

#pragma unroll
        for (int j = 0; j < 8; j++) {
            o[j][0] *= f0; o[j][1] *= f0; o[j][2] *= f1; o[j][3] *= f1;
        }
        __syncwarp();

#pragma unroll
        for (int ks = 0; ks < 2; ks++) {
            uint32_t ph0, ph1, ph2, ph3, pl0, pl1, pl2, pl3;
            ldm_x4(ph0, ph1, ph2, ph3, pah + (uint32_t)(ks * 32));
            ldm_x4(pl0, pl1, pl2, pl3, pal + (uint32_t)(ks * 32));
#pragma unroll
            for (int j = 0; j < 8; j++) {
                uint32_t vh0, vh1, vl0, vl1;
                uint32_t off = (uint32_t)(ks * 16 * VST * 2 + j * 16);
                ldmT_x2(vh0, vh1, vhb + off);
                ldmT_x2(vl0, vl1, vlb + off);
                mma16(o[j], pl0, pl1, pl2, pl3, vh0, vh1);
                mma16(o[j], ph0, ph1, ph2, ph3, vl0, vl1);
                mma16(o[j], ph0, ph1, ph2, ph3, vh0, vh1);
            }
        }
        __syncthreads();
    }

    float il0 = 1.f / l0, il1 = 1.f / l1;
    size_t base0 = ((size_t)b * SEQ + q0 + w * 16 + g) * EMBED + h * HDIM;
    size_t base1 = base0 + (size_t)8 * EMBED;
#pragma unroll
    for (int j = 0; j < 8; j++) {
        int col = j * 8 + 2 * t4;
        *(float2*)&g_attn[base0 + col] = make_float2(o[j][0] * il0, o[j][1] * il0);
        *(float2*)&g_attn[base1 + col] = make_float2(o[j][2] * il1, o[j][3] * il1);
    }
}

// ---------------------------------------------------------------------------
extern "C" void kernel_launch(void* const* d_in, const int* in_sizes, int n_in,
                              void* d_out, int out_size)
{
    const float* x    = (const float*)d_in[0];
    const int*   mask = (const int*)  d_in[1];
    const float* Wq   = (const float*)d_in[2];
    const float* bq   = (const float*)d_in[3];
    const float* Wk   = (const float*)d_in[4];
    const float* bk   = (const float*)d_in[5];
    const float* Wv   = (const float*)d_in[6];
    const float* bv   = (const float*)d_in[7];
    const float* Wo   = (const float*)d_in[8];
    const float* bo   = (const float*)d_in[9];
    float* out = (float*)d_out;

    cudaFuncSetAttribute(attn_bf16,
                         cudaFuncAttributeMaxDynamicSharedMemorySize, ATTN_SMEM_B);
    cudaFuncSetAttribute(gemm_db,
                         cudaFuncAttributeMaxDynamicSharedMemorySize, GEMM_SMEM);

    dim3 gg(EMBED / 128, MTOT / 128);    // (8, 32) = 256 CTAs
    gemm_db<<<gg, 256, GEMM_SMEM>>>(x, Wq, bq, nullptr, 0);
    gemm_db<<<gg, 256, GEMM_SMEM>>>(x, Wk, bk, nullptr, 1);
    gemm_db<<<gg, 256, GEMM_SMEM>>>(x, Wv, bv, nullptr, 2);

    attn_bf16<<<dim3(SEQ / AQ, BATCH * NHEAD), 256, ATTN_SMEM_B>>>(mask);

    gemm_db<<<gg, 256, GEMM_SMEM>>>(nullptr, Wo, bo, out, 3);
}

// round 14
// speedup vs baseline: 1.6426x; 1.0061x over previous
#include <cuda_runtime.h>
#include <cuda_bf16.h>
#include <cstdint>

#define EMBED 1024
#define NHEAD 16
#define HDIM  64
#define BATCH 2
#define SEQ   2048
#define MTOT  (BATCH*SEQ)   /* 4096 */

// Scratch (device globals: allocation-free per harness rules)
__device__ float g_q[MTOT*EMBED];            // fp32, [B,H,S,Dh]
__device__ float g_attn[MTOT*EMBED];         // fp32, [B,S,E]
__device__ __nv_bfloat16 g_k_hi[MTOT*EMBED]; // bf16 split, [B,H,S,Dh]
__device__ __nv_bfloat16 g_k_lo[MTOT*EMBED];
__device__ __nv_bfloat16 g_v_hi[MTOT*EMBED];
__device__ __nv_bfloat16 g_v_lo[MTOT*EMBED];

// ---------------------------------------------------------------------------
// helpers
// ---------------------------------------------------------------------------
__device__ __forceinline__ uint32_t s2u(const void* p) {
    return (uint32_t)__cvta_generic_to_shared(p);
}
__device__ __forceinline__ void ldm_x4(uint32_t& r0, uint32_t& r1, uint32_t& r2,
                                       uint32_t& r3, uint32_t addr) {
    asm volatile("ldmatrix.sync.aligned.m8n8.x4.shared.b16 {%0,%1,%2,%3}, [%4];"
                 : "=r"(r0), "=r"(r1), "=r"(r2), "=r"(r3) : "r"(addr));
}
__device__ __forceinline__ void ldmT_x4(uint32_t& r0, uint32_t& r1, uint32_t& r2,
                                        uint32_t& r3, uint32_t addr) {
    asm volatile("ldmatrix.sync.aligned.m8n8.x4.trans.shared.b16 {%0,%1,%2,%3}, [%4];"
                 : "=r"(r0), "=r"(r1), "=r"(r2), "=r"(r3) : "r"(addr));
}
__device__ __forceinline__ void mma16(float* c, uint32_t a0, uint32_t a1,
                                      uint32_t a2, uint32_t a3,
                                      uint32_t b0, uint32_t b1) {
    asm volatile(
        "mma.sync.aligned.m16n8k16.row.col.f32.bf16.bf16.f32 "
        "{%0,%1,%2,%3}, {%4,%5,%6,%7}, {%8,%9}, {%0,%1,%2,%3};"
        : "+f"(c[0]), "+f"(c[1]), "+f"(c[2]), "+f"(c[3])
        : "r"(a0), "r"(a1), "r"(a2), "r"(a3), "r"(b0), "r"(b1));
}
__device__ __forceinline__ void cp16(uint32_t dst, const void* src) {
    asm volatile("cp.async.cg.shared.global [%0], [%1], 16;" :: "r"(dst), "l"(src));
}
#define CP_COMMIT() asm volatile("cp.async.commit_group;")
#define CP_WAIT0()  asm volatile("cp.async.wait_group 0;")
#define CP_WAIT1()  asm volatile("cp.async.wait_group 1;")

// split fp32x4 -> (hi bf16x2 pair, lo bf16x2 pair)
__device__ __forceinline__ void split4(float4 v,
        __nv_bfloat162& h01, __nv_bfloat162& h23,
        __nv_bfloat162& l01, __nv_bfloat162& l23) {
    h01 = __floats2bfloat162_rn(v.x, v.y);
    h23 = __floats2bfloat162_rn(v.z, v.w);
    float2 f01 = __bfloat1622float2(h01);
    float2 f23 = __bfloat1622float2(h23);
    l01 = __floats2bfloat162_rn(v.x - f01.x, v.y - f01.y);
    l23 = __floats2bfloat162_rn(v.z - f23.x, v.w - f23.y);
}
__device__ __forceinline__ void store_split2(__nv_bfloat16* ph, __nv_bfloat16* pl,
                                             size_t off, float x, float y) {
    __nv_bfloat162 h = __floats2bfloat162_rn(x, y);
    float2 hf = __bfloat1622float2(h);
    __nv_bfloat162 l = __floats2bfloat162_rn(x - hf.x, y - hf.y);
    *(__nv_bfloat162*)&ph[off] = h;
    *(__nv_bfloat162*)&pl[off] = l;
}

// ---------------------------------------------------------------------------
// GEMM (bf16x3, inline split, double-buffered smem): C = A @ W^T + bias
// 128x128 tile, kc=16, 2-stage smem, ONE barrier per chunk, 256 threads.
// B-fragments fetched pairwise via ldmatrix.x4.
// ---------------------------------------------------------------------------
#define GST 24                   /* smem k-stride in bf16 elems (16 + 8 pad) */
#define TSZb (128 * GST * 2)     /* 6144 B per tensor */
#define STGb (4 * TSZb)          /* 24576 B per stage: Ah, Al, Bh, Bl */
#define GEMM_SMEM (2 * STGb)     /* 49152 B */
#define NCHUNK 64

__global__ __launch_bounds__(256, 2) void gemm_db(
    const float* __restrict__ Ain, const float* __restrict__ W,
    const float* __restrict__ bias, float* __restrict__ Oout, int mode)
{
    extern __shared__ char gsm[];
    const uint32_t smu = s2u(gsm);

    const float* A = (mode == 3) ? g_attn : Ain;

    const int t    = threadIdx.x;
    const int lane = t & 31;
    const int w    = t >> 5;
    const int wm   = w >> 2;        // 0..1  (64 rows each)
    const int wn   = w & 3;         // 0..3  (32 cols each)
    const int m0   = blockIdx.y * 128;
    const int n0   = blockIdx.x * 128;

    const int t4    = lane & 3;
    const int g     = lane >> 2;
    const int row_l = (lane & 7) + ((lane >> 3) & 1) * 8;
    const int khalf = lane >> 4;

    const uint32_t a_off = (uint32_t)(((wm * 64 + row_l) * GST + khalf * 8) * 2);
    // x4 B-frag: lanes 0-7 rows(+0) k0, 8-15 rows(+0) k8, 16-23 rows(+8) k0, 24-31 rows(+8) k8
    const uint32_t b_off4 = (uint32_t)(((wn * 32 + (lane & 7) + ((lane >> 4) & 1) * 8) * GST
                                        + ((lane >> 3) & 1) * 8) * 2);

    float c[4][4][4];
#pragma unroll
    for (int mi = 0; mi < 4; mi++)
#pragma unroll
        for (int nj = 0; nj < 4; nj++)
#pragma unroll
            for (int i = 0; i < 4; i++) c[mi][nj][i] = 0.f;

    // chunk-load indices: 512 float4 per matrix per chunk, 2 per thread
    const int r0g = (0 * 256 + t) >> 2, s0g = (0 * 256 + t) & 3;
    const int r1g = (1 * 256 + t) >> 2, s1g = (1 * 256 + t) & 3;

    float4 av0, av1, bv0, bv1;

    auto ldg_chunk = [&](int kb) {
        const int k0 = kb * 16;
        av0 = *(const float4*)&A[(size_t)(m0 + r0g) * EMBED + k0 + s0g * 4];
        av1 = *(const float4*)&A[(size_t)(m0 + r1g) * EMBED + k0 + s1g * 4];
        bv0 = *(const float4*)&W[(size_t)(n0 + r0g) * EMBED + k0 + s0g * 4];
        bv1 = *(const float4*)&W[(size_t)(n0 + r1g) * EMBED + k0 + s1g * 4];
    };

    auto sts_chunk = [&](int stage) {
        char* base = gsm + stage * STGb;
        __nv_bfloat16* Ash = (__nv_bfloat16*)(base);
        __nv_bfloat16* Asl = (__nv_bfloat16*)(base + TSZb);
        __nv_bfloat16* Bsh = (__nv_bfloat16*)(base + 2 * TSZb);
        __nv_bfloat16* Bsl = (__nv_bfloat16*)(base + 3 * TSZb);
        __nv_bfloat162 h01, h23, l01, l23;
        split4(av0, h01, h23, l01, l23);
        *(__nv_bfloat162*)&Ash[r0g * GST + s0g * 4]     = h01;
        *(__nv_bfloat162*)&Ash[r0g * GST + s0g * 4 + 2] = h23;
        *(__nv_bfloat162*)&Asl[r0g * GST + s0g * 4]     = l01;
        *(__nv_bfloat162*)&Asl[r0g * GST + s0g * 4 + 2] = l23;
        split4(av1, h01, h23, l01, l23);
        *(__nv_bfloat162*)&Ash[r1g * GST + s1g * 4]     = h01;
        *(__nv_bfloat162*)&Ash[r1g * GST + s1g * 4 + 2] = h23;
        *(__nv_bfloat162*)&Asl[r1g * GST + s1g * 4]     = l01;
        *(__nv_bfloat162*)&Asl[r1g * GST + s1g * 4 + 2] = l23;
        split4(bv0, h01, h23, l01, l23);
        *(__nv_bfloat162*)&Bsh[r0g * GST + s0g * 4]     = h01;
        *(__nv_bfloat162*)&Bsh[r0g * GST + s0g * 4 + 2] = h23;
        *(__nv_bfloat162*)&Bsl[r0g * GST + s0g * 4]     = l01;
        *(__nv_bfloat162*)&Bsl[r0g * GST + s0g * 4 + 2] = l23;
        split4(bv1, h01, h23, l01, l23);
        *(__nv_bfloat162*)&Bsh[r1g * GST + s1g * 4]     = h01;
        *(__nv_bfloat162*)&Bsh[r1g * GST + s1g * 4 + 2] = h23;
        *(__nv_bfloat162*)&Bsl[r1g * GST + s1g * 4]     = l01;
        *(__nv_bfloat162*)&Bsl[r1g * GST + s1g * 4 + 2] = l23;
    };

    // prologue: chunk0 -> stage0; prefetch chunk1 into regs
    ldg_chunk(0);
    sts_chunk(0);
    ldg_chunk(1);
    __syncthreads();

    for (int kb = 0; kb < NCHUNK; kb++) {
        const uint32_t sb = smu + (uint32_t)((kb & 1) * STGb);

        // MMA on stage kb&1 — B frags pairwise via x4
        uint32_t Bh[2][4], Bl[2][4];
#pragma unroll
        for (int nj2 = 0; nj2 < 2; nj2++) {
            ldm_x4(Bh[nj2][0], Bh[nj2][1], Bh[nj2][2], Bh[nj2][3],
                   sb + 2 * TSZb + b_off4 + (uint32_t)(nj2 * 16 * GST * 2));
            ldm_x4(Bl[nj2][0], Bl[nj2][1], Bl[nj2][2], Bl[nj2][3],
                   sb + 3 * TSZb + b_off4 + (uint32_t)(nj2 * 16 * GST * 2));
        }
#pragma unroll
        for (int mi = 0; mi < 4; mi++) {
            uint32_t ah0, ah1, ah2, ah3, al0, al1, al2, al3;
            uint32_t ao = a_off + (uint32_t)(mi * 16 * GST * 2);
            ldm_x4(ah0, ah1, ah2, ah3, sb + ao);
            ldm_x4(al0, al1, al2, al3, sb + TSZb + ao);
#pragma unroll
            for (int nj = 0; nj < 4; nj++) {
                const uint32_t* bh = &Bh[nj >> 1][(nj & 1) * 2];
                const uint32_t* bl = &Bl[nj >> 1][(nj & 1) * 2];
                mma16(c[mi][nj], al0, al1, al2, al3, bh[0], bh[1]);
                mma16(c[mi][nj], ah0, ah1, ah2, ah3, bl[0], bl[1]);
                mma16(c[mi][nj], ah0, ah1, ah2, ah3, bh[0], bh[1]);
            }
        }

        // stage kb+1: split regs -> other buffer; prefetch kb+2; single barrier
        if (kb + 1 < NCHUNK) {
            sts_chunk((kb + 1) & 1);
            if (kb + 2 < NCHUNK) ldg_chunk(kb + 2);
            __syncthreads();
        }
    }

    // epilogue
#pragma unroll
    for (int mi = 0; mi < 4; mi++) {
        int r0 = m0 + wm * 64 + mi * 16 + g;
        int r1 = r0 + 8;
#pragma unroll
        for (int nj = 0; nj < 4; nj++) {
            int col = n0 + wn * 32 + nj * 8 + 2 * t4;
            float bb0 = bias[col], bb1 = bias[col + 1];
            float v00 = c[mi][nj][0] + bb0, v01 = c[mi][nj][1] + bb1;
            float v10 = c[mi][nj][2] + bb0, v11 = c[mi][nj][3] + bb1;
            if (mode == 3) {
                *(float2*)&Oout[(size_t)r0 * EMBED + col] = make_float2(v00, v01);
                *(float2*)&Oout[(size_t)r1 * EMBED + col] = make_float2(v10, v11);
            } else {
                int h  = col >> 6, dh = col & 63;
                int b0i = r0 >> 11, s0i = r0 & 2047;
                int b1i = r1 >> 11, s1i = r1 & 2047;
                size_t o0 = (((size_t)(b0i * NHEAD + h)) * SEQ + s0i) * HDIM + dh;
                size_t o1 = (((size_t)(b1i * NHEAD + h)) * SEQ + s1i) * HDIM + dh;
                if (mode == 0) {
                    *(float2*)&g_q[o0] = make_float2(v00, v01);
                    *(float2*)&g_q[o1] = make_float2(v10, v11);
                } else if (mode == 1) {
                    store_split2(g_k_hi, g_k_lo, o0, v00, v01);
                    store_split2(g_k_hi, g_k_lo, o1, v10, v11);
                } else {
                    store_split2(g_v_hi, g_v_lo, o0, v00, v01);
                    store_split2(g_v_hi, g_v_lo, o1, v10, v11);
                }
            }
        }
    }
}

// ---------------------------------------------------------------------------
// Flash attention (bf16x3): AQ=128 (8 warps x 16 rows), BK=32,
// cp.async double-buffered pre-split K/V, in-register online softmax,
// P staged via smem. K and V fragments fetched pairwise via ldmatrix.x4.
// ---------------------------------------------------------------------------
#define AQ  128
#define AK  32
#define NIT (SEQ / AK)   /* 64 */
#define QST 72
#define PST 40
#define KST 72
#define VST 72

#define OQH 0
#define OQL 18432
#define OPH 36864
#define OPL 47104
#define OKH 57344
#define OKL 66560
#define OVH 75776
#define OVL 84992
#define OMK 94208
#define ATTN_SMEM_B 94464
#define KBUF 4608

__global__ __launch_bounds__(256, 2) void attn_bf16(const int* __restrict__ mask)
{
    extern __shared__ char smraw[];
    const uint32_t sm_u = s2u(smraw);

    __nv_bfloat16* Qh = (__nv_bfloat16*)(smraw + OQH);
    __nv_bfloat16* Ql = (__nv_bfloat16*)(smraw + OQL);
    __nv_bfloat16* Ph = (__nv_bfloat16*)(smraw + OPH);
    __nv_bfloat16* Pl = (__nv_bfloat16*)(smraw + OPL);
    int* mks = (int*)(smraw + OMK);

    const int t    = threadIdx.x;
    const int lane = t & 31;
    const int w    = t >> 5;
    const int bh   = blockIdx.y;
    const int b    = bh >> 4;
    const int h    = bh & 15;
    const int q0   = blockIdx.x * AQ;

    const int t4    = lane & 3;
    const int g     = lane >> 2;
    const int row_l = (lane & 7) + ((lane >> 3) & 1) * 8;
    const int khalf = lane >> 4;

    const float* Qg = g_q + (size_t)bh * SEQ * HDIM;
    const __nv_bfloat16* Kgh = g_k_hi + (size_t)bh * SEQ * HDIM;
    const __nv_bfloat16* Kgl = g_k_lo + (size_t)bh * SEQ * HDIM;
    const __nv_bfloat16* Vgh = g_v_hi + (size_t)bh * SEQ * HDIM;
    const __nv_bfloat16* Vgl = g_v_lo + (size_t)bh * SEQ * HDIM;

    const int crow = t >> 3, cseg = t & 7;
    const uint32_t csoff = (uint32_t)((crow * KST + cseg * 8) * 2);
    const size_t   cgbase = (size_t)crow * HDIM + cseg * 8;

    const uint32_t qah = sm_u + OQH + (uint32_t)(((w * 16 + row_l) * QST + khalf * 8) * 2);
    const uint32_t qal = sm_u + OQL + (uint32_t)(((w * 16 + row_l) * QST + khalf * 8) * 2);
    const uint32_t pah = sm_u + OPH + (uint32_t)(((w * 16 + row_l) * PST + khalf * 8) * 2);
    const uint32_t pal = sm_u + OPL + (uint32_t)(((w * 16 + row_l) * PST + khalf * 8) * 2);
    // x4 K-frag: lanes 0-7 rows(+0) k0, 8-15 rows(+0) k8, 16-23 rows(+8) k0, 24-31 rows(+8) k8
    const uint32_t kboff4 = (uint32_t)((((lane & 7) + ((lane >> 4) & 1) * 8) * KST
                                        + ((lane >> 3) & 1) * 8) * 2);
    // x4 trans V-frag: lanes 0-7 Vrow(+0) col0, 8-15 Vrow(+8) col0, 16-23 Vrow(+0) col+8, 24-31 Vrow(+8) col+8
    const uint32_t vboff4 = (uint32_t)((((lane & 7) + ((lane >> 3) & 1) * 8) * VST) * 2
                                       + ((lane >> 4) & 1) * 16);

    cp16(sm_u + OKH + csoff, Kgh + cgbase);
    cp16(sm_u + OKL + csoff, Kgl + cgbase);
    cp16(sm_u + OVH + csoff, Vgh + cgbase);
    cp16(sm_u + OVL + csoff, Vgl + cgbase);
    if (t < 8) cp16(sm_u + OMK + t * 16, mask + b * SEQ + t * 4);
    CP_COMMIT();

#pragma unroll
    for (int l = 0; l < 8; l++) {
        int e = l * 256 + t, row = e >> 4, seg = e & 15;
        float4 v = *(const float4*)&Qg[(size_t)(q0 + row) * HDIM + seg * 4];
        v.x *= 0.125f; v.y *= 0.125f; v.z *= 0.125f; v.w *= 0.125f;
        __nv_bfloat162 h01, h23, l01, l23;
        split4(v, h01, h23, l01, l23);
        int off = row * QST + seg * 4;
        *(__nv_bfloat162*)&Qh[off]     = h01;
        *(__nv_bfloat162*)&Qh[off + 2] = h23;
        *(__nv_bfloat162*)&Ql[off]     = l01;
        *(__nv_bfloat162*)&Ql[off + 2] = l23;
    }

    float o[8][4];
#pragma unroll
    for (int j = 0; j < 8; j++)
#pragma unroll
        for (int i = 0; i < 4; i++) o[j][i] = 0.f;
    float m0 = -1e30f, m1 = -1e30f, l0 = 0.f, l1 = 0.f;

    __syncthreads();

    for (int it = 0; it < NIT; it++) {
        const int buf = it & 1;
        if (it + 1 < NIT) {
            const int nb = buf ^ 1;
            const size_t gb = cgbase + (size_t)(it + 1) * AK * HDIM;
            const uint32_t so = (uint32_t)(nb * KBUF) + csoff;
            cp16(sm_u + OKH + so, Kgh + gb);
            cp16(sm_u + OKL + so, Kgl + gb);
            cp16(sm_u + OVH + so, Vgh + gb);
            cp16(sm_u + OVL + so, Vgl + gb);
            if (t < 8) cp16(sm_u + OMK + (uint32_t)(nb * 128 + t * 16),
                            mask + b * SEQ + (it + 1) * AK + t * 4);
            CP_COMMIT();
            CP_WAIT1();
        } else {
            CP_WAIT0();
        }
        __syncthreads();

        const uint32_t khb = sm_u + OKH + (uint32_t)(buf * KBUF) + kboff4;
        const uint32_t klb = sm_u + OKL + (uint32_t)(buf * KBUF) + kboff4;
        const uint32_t vhb = sm_u + OVH + (uint32_t)(buf * KBUF) + vboff4;
        const uint32_t vlb = sm_u + OVL + (uint32_t)(buf * KBUF) + vboff4;
        const int* mk = mks + buf * 32;

        float s[4][4];
#pragma unroll
        for (int j = 0; j < 4; j++)
#pragma unroll
            for (int i = 0; i < 4; i++) s[j][i] = 0.f;

#pragma unroll
        for (int ks = 0; ks < 4; ks++) {
            uint32_t ah0, ah1, ah2, ah3, al0, al1, al2, al3;
            ldm_x4(ah0, ah1, ah2, ah3, qah + (uint32_t)(ks * 32));
            ldm_x4(al0, al1, al2, al3, qal + (uint32_t)(ks * 32));
#pragma unroll
            for (int j2 = 0; j2 < 2; j2++) {
                uint32_t bh[4], bl[4];
                uint32_t off = (uint32_t)(j2 * 16 * KST * 2 + ks * 32);
                ldm_x4(bh[0], bh[1], bh[2], bh[3], khb + off);
                ldm_x4(bl[0], bl[1], bl[2], bl[3], klb + off);
                mma16(s[2 * j2],     al0, al1, al2, al3, bh[0], bh[1]);
                mma16(s[2 * j2],     ah0, ah1, ah2, ah3, bl[0], bl[1]);
                mma16(s[2 * j2],     ah0, ah1, ah2, ah3, bh[0], bh[1]);
                mma16(s[2 * j2 + 1], al0, al1, al2, al3, bh[2], bh[3]);
                mma16(s[2 * j2 + 1], ah0, ah1, ah2, ah3, bl[2], bl[3]);
                mma16(s[2 * j2 + 1], ah0, ah1, ah2, ah3, bh[2], bh[3]);
            }
        }

        float mx0 = -1e30f, mx1 = -1e30f;
#pragma unroll
        for (int j = 0; j < 4; j++) {
            int cb = j * 8 + 2 * t4;
            if (mk[cb] == 0)     { s[j][0] = -1e9f; s[j][2] = -1e9f; }
            if (mk[cb + 1] == 0) { s[j][1] = -1e9f; s[j][3] = -1e9f; }
            mx0 = fmaxf(mx0, fmaxf(s[j][0], s[j][1]));
            mx1 = fmaxf(mx1, fmaxf(s[j][2], s[j][3]));
        }
        mx0 = fmaxf(mx0, __shfl_xor_sync(0xffffffffu, mx0, 1));
        mx0 = fmaxf(mx0, __shfl_xor_sync(0xffffffffu, mx0, 2));
        mx1 = fmaxf(mx1, __shfl_xor_sync(0xffffffffu, mx1, 1));
        mx1 = fmaxf(mx1, __shfl_xor_sync(0xffffffffu, mx1, 2));

        float mn0 = fmaxf(m0, mx0), mn1 = fmaxf(m1, mx1);
        float f0 = __expf(m0 - mn0), f1 = __expf(m1 - mn1);
        m0 = mn0; m1 = mn1;

        float sum0 = 0.f, sum1 = 0.f;
        int pr0 = (w * 16 + g) * PST;
        int pr1 = (w * 16 + g + 8) * PST;
#pragma unroll
        for (int j = 0; j < 4; j++) {
            int cb = j * 8 + 2 * t4;
            float p00 = __expf(s[j][0] - m0);
            float p01 = __expf(s[j][1] - m0);
            float p10 = __expf(s[j][2] - m1);
            float p11 = __expf(s[j][3] - m1);
            sum0 += p00 + p01;
            sum1 += p10 + p11;
            __nv_bfloat162 h0 = __floats2bfloat162_rn(p00, p01);
            __nv_bfloat162 h1 = __floats2bfloat162_rn(p10, p11);
            float2 hf0 = __bfloat1622float2(h0);
            float2 hf1 = __bfloat1622float2(h1);
            *(__nv_bfloat162*)&Ph[pr0 + cb] = h0;
            *(__nv_bfloat162*)&Ph[pr1 + cb] = h1;
            *(__nv_bfloat162*)&Pl[pr0 + cb] = __floats2bfloat162_rn(p00 - hf0.x, p01 - hf0.y);
            *(__nv_bfloat162*)&Pl[pr1 + cb] = __floats2bfloat162_rn(p10 - hf1.x, p11 - hf1.y);
        }
        sum0 += __shfl_xor_sync(0xffffffffu, sum0, 1);
        sum0 += __shfl_xor_sync(0xffffffffu, sum0, 2);
        sum1 += __shfl_xor_sync(0xffffffffu, sum1, 1);
        sum1 += __shfl_xor_sync(0xffffffffu, sum1, 2);
        l0 = l0 * f0 + sum0;
        l1 = l1 * f1 + sum1;

#pragma unroll
        for (int j = 0; j < 8; j++) {
            o[j][0] *= f0; o[j][1] *= f0; o[j][2] *= f1; o[j][3] *= f1;
        }
        __syncwarp();

#pragma unroll
        for (int ks = 0; ks < 2; ks++) {
            uint32_t ph0, ph1, ph2, ph3, pl0, pl1, pl2, pl3;
            ldm_x4(ph0, ph1, ph2, ph3, pah + (uint32_t)(ks * 32));
            ldm_x4(pl0, pl1, pl2, pl3, pal + (uint32_t)(ks * 32));
#pragma unroll
            for (int j2 = 0; j2 < 4; j2++) {
                uint32_t vh[4], vl[4];
                uint32_t off = (uint32_t)(ks * 16 * VST * 2 + j2 * 32);
                ldmT_x4(vh[0], vh[1], vh[2], vh[3], vhb + off);
                ldmT_x4(vl[0], vl[1], vl[2], vl[3], vlb + off);
                mma16(o[2 * j2],     pl0, pl1, pl2, pl3, vh[0], vh[1]);
                mma16(o[2 * j2],     ph0, ph1, ph2, ph3, vl[0], vl[1]);
                mma16(o[2 * j2],     ph0, ph1, ph2, ph3, vh[0], vh[1]);
                mma16(o[2 * j2 + 1], pl0, pl1, pl2, pl3, vh[2], vh[3]);
                mma16(o[2 * j2 + 1], ph0, ph1, ph2, ph3, vl[2], vl[3]);
                mma16(o[2 * j2 + 1], ph0, ph1, ph2, ph3, vh[2], vh[3]);
            }
        }
        __syncthreads();
    }

    float il0 = 1.f / l0, il1 = 1.f / l1;
    size_t base0 = ((size_t)b * SEQ + q0 + w * 16 + g) * EMBED + h * HDIM;
    size_t base1 = base0 + (size_t)8 * EMBED;
#pragma unroll
    for (int j = 0; j < 8; j++) {
        int col = j * 8 + 2 * t4;
        *(float2*)&g_attn[base0 + col] = make_float2(o[j][0] * il0, o[j][1] * il0);
        *(float2*)&g_attn[base1 + col] = make_float2(o[j][2] * il1, o[j][3] * il1);
    }
}

// ---------------------------------------------------------------------------
extern "C" void kernel_launch(void* const* d_in, const int* in_sizes, int n_in,
                              void* d_out, int out_size)
{
    const float* x    = (const float*)d_in[0];
    const int*   mask = (const int*)  d_in[1];
    const float* Wq   = (const float*)d_in[2];
    const float* bq   = (const float*)d_in[3];
    const float* Wk   = (const float*)d_in[4];
    const float* bk   = (const float*)d_in[5];
    const float* Wv   = (const float*)d_in[6];
    const float* bv   = (const float*)d_in[7];
    const float* Wo   = (const float*)d_in[8];
    const float* bo   = (const float*)d_in[9];
    float* out = (float*)d_out;

    cudaFuncSetAttribute(attn_bf16,
                         cudaFuncAttributeMaxDynamicSharedMemorySize, ATTN_SMEM_B);
    cudaFuncSetAttribute(gemm_db,
                         cudaFuncAttributeMaxDynamicSharedMemorySize, GEMM_SMEM);

    dim3 gg(EMBED / 128, MTOT / 128);    // (8, 32) = 256 CTAs
    gemm_db<<<gg, 256, GEMM_SMEM>>>(x, Wq, bq, nullptr, 0);
    gemm_db<<<gg, 256, GEMM_SMEM>>>(x, Wk, bk, nullptr, 1);
    gemm_db<<<gg, 256, GEMM_SMEM>>>(x, Wv, bv, nullptr, 2);

    attn_bf16<<<dim3(SEQ / AQ, BATCH * NHEAD), 256, ATTN_SMEM_B>>>(mask);

    gemm_db<<<gg, 256, GEMM_SMEM>>>(nullptr, Wo, bo, out, 3);
}